// round 2
// baseline (speedup 1.0000x reference)
#include <cuda_runtime.h>
#include <cstdint>
#include <cstddef>

// Problem constants
#define BB 256      // batch
#define SS 512      // encoder sequence length
#define FF 64       // feature dim
#define HH 1024     // hidden dim
#define GG 4096     // 4*H gate rows
#define KTOT 1088   // F + H
#define TT 64       // prediction length

// GEMM tiling
#define BM 64
#define BN 64
#define BK 16
#define BNP 68          // padded Bs row (floats)
#define NCHUNK 68       // 4 chunks of x (64/16) + 64 chunks of h (1024/16)

// ---------------- device globals (scratch; no allocations allowed) ----------------
__device__ float g_Wr_enc[GG * KTOT];   // reordered [j*4+g][k] concat(W_ih, W_hh)
__device__ float g_Wr_dec[GG * KTOT];
__device__ float g_br_enc[GG];          // reordered combined bias
__device__ float g_br_dec[GG];
__device__ float g_h[2][BB * HH];       // ping-pong hidden state
__device__ float g_c[2][BB * HH];       // ping-pong cell state
__device__ float g_x[BB * FF];          // decoder feedback input

// ---------------- helpers ----------------
__device__ __forceinline__ void cp16(uint32_t dst, const void* src) {
    asm volatile("cp.async.ca.shared.global [%0], [%1], 16;\n" :: "r"(dst), "l"(src));
}
__device__ __forceinline__ void cp_commit() { asm volatile("cp.async.commit_group;\n"); }
__device__ __forceinline__ void cp_wait0()  { asm volatile("cp.async.wait_group 0;\n" ::: "memory"); }

__device__ __forceinline__ float sigf(float x)   { return 1.f / (1.f + __expf(-x)); }
__device__ __forceinline__ float tanhf_(float x) { return 2.f / (1.f + __expf(-2.f * x)) - 1.f; }

// ---------------- prep: reorder weights so 4 gates of one unit are adjacent rows ----
// Wr[(j*4+g)][k] = k < F ? W_ih[g*H+j][k] : W_hh[g*H+j][k-F]
// br[j*4+g]      = b_ih[g*H+j] + b_hh[g*H+j]
__global__ void prep_kernel(const float* __restrict__ Wih, const float* __restrict__ Whh,
                            const float* __restrict__ bih, const float* __restrict__ bhh,
                            int dec)
{
    float* Wr = dec ? g_Wr_dec : g_Wr_enc;
    float* br = dec ? g_br_dec : g_br_enc;
    const int total = GG * KTOT;
    for (int idx = blockIdx.x * blockDim.x + threadIdx.x; idx < total;
         idx += gridDim.x * blockDim.x) {
        int r = idx / KTOT, k = idx - r * KTOT;
        int j = r >> 2, gg = r & 3;
        int srow = gg * HH + j;
        Wr[idx] = (k < FF) ? Wih[srow * FF + k] : Whh[(size_t)srow * HH + (k - FF)];
    }
    for (int r = blockIdx.x * blockDim.x + threadIdx.x; r < GG;
         r += gridDim.x * blockDim.x) {
        int j = r >> 2, gg = r & 3;
        br[r] = bih[gg * HH + j] + bhh[gg * HH + j];
    }
}

__global__ void zero_kernel()
{
    for (int i = blockIdx.x * blockDim.x + threadIdx.x; i < BB * HH;
         i += gridDim.x * blockDim.x) {
        g_h[0][i] = 0.f;
        g_c[0][i] = 0.f;
    }
}

// ---------------- fused LSTM step ----------------
// gates[256 x 4096] = [x_t | h_in] (256 x 1088) @ Wr^T  (+ br), then elementwise LSTM.
// Block tile: 64 batch x 64 gate-cols (= 16 complete units). grid (64, 4) = 256 blocks.
// Thread: tn = 0..15 (one unit: 4 gate cols), tm = 0..7 (8 batch rows). 8x4 acc.
__global__ __launch_bounds__(128)
void lstm_step_kernel(const float* __restrict__ x_all, int t, int xmode, int dec, int pp)
{
    const float* __restrict__ Wr   = dec ? g_Wr_dec : g_Wr_enc;
    const float* __restrict__ br   = dec ? g_br_dec : g_br_enc;
    const float* __restrict__ h_in = g_h[pp];
    const float* __restrict__ c_in = g_c[pp];
    float* __restrict__ h_out = g_h[pp ^ 1];
    float* __restrict__ c_out = g_c[pp ^ 1];

    __shared__ __align__(16) float As[2][BM * BK];     // [m][k]
    __shared__ __align__(16) float Bs[2][BK * BNP];    // [k][n] padded to 68

    const int tid = threadIdx.x;
    const int tn  = tid & 15;
    const int tm  = tid >> 4;
    const int n0  = blockIdx.x * BN;   // gate-col base
    const int m0  = blockIdx.y * BM;   // batch base

    float acc[8][4];
#pragma unroll
    for (int i = 0; i < 8; i++)
#pragma unroll
        for (int g = 0; g < 4; g++) acc[i][g] = 0.f;

    // loader index mapping (shared by A and B): idx -> (row = idx/4, kq = idx%4)
    int lM[2], lK[2];
#pragma unroll
    for (int i = 0; i < 2; i++) { int idx = tid + i * 128; lM[i] = idx >> 2; lK[i] = (idx & 3) * 4; }

    auto issueA = [&](int chunk, int s) {
#pragma unroll
        for (int i = 0; i < 2; i++) {
            const float* src;
            int m = lM[i];
            if (chunk < 4) {
                int k = chunk * BK + lK[i];
                src = (xmode == 0)
                    ? (x_all + (size_t)(m0 + m) * (SS * FF) + (size_t)t * FF + k)
                    : (g_x + (m0 + m) * FF + k);
            } else {
                int k = (chunk - 4) * BK + lK[i];
                src = h_in + (size_t)(m0 + m) * HH + k;
            }
            uint32_t dst = (uint32_t)__cvta_generic_to_shared(&As[s][m * BK + lK[i]]);
            cp16(dst, src);
        }
        cp_commit();
    };

    float4 breg[2];
    auto ldgB = [&](int chunk) {
        int koff = (chunk < 4) ? chunk * BK : FF + (chunk - 4) * BK;
#pragma unroll
        for (int i = 0; i < 2; i++) {
            breg[i] = *reinterpret_cast<const float4*>(
                Wr + (size_t)(n0 + lM[i]) * KTOT + koff + lK[i]);
        }
    };
    auto stsB = [&](int s) {
#pragma unroll
        for (int i = 0; i < 2; i++) {
            int kk = lK[i], n = lM[i];
            Bs[s][(kk + 0) * BNP + n] = breg[i].x;
            Bs[s][(kk + 1) * BNP + n] = breg[i].y;
            Bs[s][(kk + 2) * BNP + n] = breg[i].z;
            Bs[s][(kk + 3) * BNP + n] = breg[i].w;
        }
    };

    // preload chunk 0
    issueA(0, 0);
    ldgB(0);
    stsB(0);

    for (int c = 0; c < NCHUNK; c++) {
        int s = c & 1;
        cp_wait0();
        __syncthreads();                 // A(c) + B(c) visible; prior-stage readers done
        if (c + 1 < NCHUNK) {
            issueA(c + 1, s ^ 1);        // async fill of the other stage
            ldgB(c + 1);                 // stage B in registers
        }
#pragma unroll
        for (int k = 0; k < BK; k++) {
            float a[8];
#pragma unroll
            for (int i = 0; i < 8; i++) a[i] = As[s][(tm * 8 + i) * BK + k];
            const float4 bv = *reinterpret_cast<const float4*>(&Bs[s][k * BNP + tn * 4]);
#pragma unroll
            for (int i = 0; i < 8; i++) {
                acc[i][0] += a[i] * bv.x;
                acc[i][1] += a[i] * bv.y;
                acc[i][2] += a[i] * bv.z;
                acc[i][3] += a[i] * bv.w;
            }
        }
        if (c + 1 < NCHUNK) stsB(s ^ 1); // safe: other stage, prior readers synced out
    }

    // fused LSTM epilogue: this thread owns all 4 gates of unit j for 8 batch rows
    const int j = (n0 >> 2) + tn;
    const float4 bb = *reinterpret_cast<const float4*>(br + 4 * j);
#pragma unroll
    for (int i = 0; i < 8; i++) {
        int b = m0 + tm * 8 + i;
        float iv = sigf(acc[i][0] + bb.x);
        float fv = sigf(acc[i][1] + bb.y);
        float gv = tanhf_(acc[i][2] + bb.z);
        float ov = sigf(acc[i][3] + bb.w);
        float cn = fv * c_in[(size_t)b * HH + j] + iv * gv;
        c_out[(size_t)b * HH + j] = cn;
        h_out[(size_t)b * HH + j] = ov * tanhf_(cn);
    }
}

// ---------------- fc: pred = h @ W_fc^T + b_fc; feeds g_x and writes output ---------
__global__ __launch_bounds__(64)
void fc_kernel(const float* __restrict__ Wfc, const float* __restrict__ bfc,
               float* __restrict__ out, int t, int pp)
{
    int b = blockIdx.x;
    const float* h = g_h[pp] + (size_t)b * HH;
    __shared__ __align__(16) float hs[HH];
    for (int i = threadIdx.x; i < HH / 4; i += 64)
        reinterpret_cast<float4*>(hs)[i] = reinterpret_cast<const float4*>(h)[i];
    __syncthreads();

    int f = threadIdx.x;
    float s = bfc[f];
    const float4* w4 = reinterpret_cast<const float4*>(Wfc + (size_t)f * HH);
    const float4* h4 = reinterpret_cast<const float4*>(hs);
#pragma unroll 4
    for (int k = 0; k < HH / 4; k++) {
        float4 wv = w4[k], hv = h4[k];
        s += wv.x * hv.x + wv.y * hv.y + wv.z * hv.z + wv.w * hv.w;
    }
    g_x[b * FF + f] = s;
    out[(size_t)b * TT * FF + (size_t)t * FF + f] = s;
}

// ---------------- launch ----------------
extern "C" void kernel_launch(void* const* d_in, const int* in_sizes, int n_in,
                              void* d_out, int out_size)
{
    const float* x     = (const float*)d_in[0];
    const float* Wih_e = (const float*)d_in[1];
    const float* Whh_e = (const float*)d_in[2];
    const float* bih_e = (const float*)d_in[3];
    const float* bhh_e = (const float*)d_in[4];
    const float* Wih_d = (const float*)d_in[5];
    const float* Whh_d = (const float*)d_in[6];
    const float* bih_d = (const float*)d_in[7];
    const float* bhh_d = (const float*)d_in[8];
    const float* Wfc   = (const float*)d_in[9];
    const float* bfc   = (const float*)d_in[10];
    float* out = (float*)d_out;

    prep_kernel<<<1024, 256>>>(Wih_e, Whh_e, bih_e, bhh_e, 0);
    prep_kernel<<<1024, 256>>>(Wih_d, Whh_d, bih_d, bhh_d, 1);
    zero_kernel<<<512, 256>>>();

    dim3 grid(GG / BN, BB / BM);   // (64, 4)
    int pp = 0;
    for (int t = 0; t < SS; t++) {
        lstm_step_kernel<<<grid, 128>>>(x, t, /*xmode=*/0, /*dec=*/0, pp);
        pp ^= 1;
    }
    for (int t = 0; t < TT; t++) {
        // t==0: x is the last encoder input; afterwards x comes from g_x (fed back)
        lstm_step_kernel<<<grid, 128>>>(x, SS - 1, (t == 0) ? 0 : 1, /*dec=*/1, pp);
        pp ^= 1;
        fc_kernel<<<BB, 64>>>(Wfc, bfc, out, t, pp);
    }
}

// round 5
// speedup vs baseline: 1.7028x; 1.7028x over previous
#include <cuda_runtime.h>
#include <cuda_bf16.h>
#include <cstdint>
#include <cstddef>

// Problem constants
#define BB 256      // batch
#define SS 512      // encoder sequence length
#define FF 64       // feature dim
#define HH 1024     // hidden dim
#define GG 4096     // 4*H gate rows
#define KTOT 1088   // F + H
#define TT 64       // prediction length

// GEMM tiling: K' = 3*1088 = 3264 (bf16-split triple product), chunk 64
#define KC 64
#define NCH 51      // 3264 / 64
#define BM 128
#define BN 64
#define STG_BYTES 24576             // A 16KB + B 8KB per stage
#define SMEM_BYTES (3 * STG_BYTES)  // 3-stage pipeline

// ---------------- device globals ----------------
__device__ __align__(16) __nv_bfloat16 g_Bh_enc[GG * KTOT];  // weights hi, rows j*4+g, K-major
__device__ __align__(16) __nv_bfloat16 g_Bl_enc[GG * KTOT];  // weights lo
__device__ __align__(16) __nv_bfloat16 g_Bh_dec[GG * KTOT];
__device__ __align__(16) __nv_bfloat16 g_Bl_dec[GG * KTOT];
__device__ __align__(16) float g_br_enc[GG];                 // combined bias, reordered
__device__ __align__(16) float g_br_dec[GG];
__device__ __align__(16) __nv_bfloat16 g_Xh[SS * BB * FF];   // encoder x, [t][b][f], hi
__device__ __align__(16) __nv_bfloat16 g_Xl[SS * BB * FF];
__device__ __align__(16) __nv_bfloat16 g_Hh[2][BB * HH];     // hidden state hi (ping-pong)
__device__ __align__(16) __nv_bfloat16 g_Hl[2][BB * HH];
__device__ __align__(16) __nv_bfloat16 g_Dxh[BB * FF];       // decoder feedback x hi
__device__ __align__(16) __nv_bfloat16 g_Dxl[BB * FF];
__device__ float g_c[BB * HH];                               // cell state (in-place)
__device__ float g_hf[BB * HH];                              // fp32 hidden (for fc)

// ---------------- helpers ----------------
__device__ __forceinline__ uint32_t smem_u32(const void* p) {
    return (uint32_t)__cvta_generic_to_shared(p);
}
__device__ __forceinline__ void cp16(uint32_t dst, const void* src) {
    asm volatile("cp.async.ca.shared.global [%0], [%1], 16;\n" :: "r"(dst), "l"(src));
}
__device__ __forceinline__ void cp_commit() { asm volatile("cp.async.commit_group;\n"); }
__device__ __forceinline__ void cp_wait0()  { asm volatile("cp.async.wait_group 0;\n" ::: "memory"); }
__device__ __forceinline__ void cp_wait1()  { asm volatile("cp.async.wait_group 1;\n" ::: "memory"); }

__device__ __forceinline__ float sigf(float x)   { return 1.f / (1.f + __expf(-x)); }
__device__ __forceinline__ float tanhf_(float x) { return 2.f / (1.f + __expf(-2.f * x)) - 1.f; }

__device__ __forceinline__ void bf16split(float v, __nv_bfloat16& hi, __nv_bfloat16& lo) {
    hi = __float2bfloat16_rn(v);
    lo = __float2bfloat16_rn(v - __bfloat162float(hi));
}

__device__ __forceinline__ void ldsm4(uint32_t* r, uint32_t addr) {
    asm volatile("ldmatrix.sync.aligned.m8n8.x4.shared.b16 {%0,%1,%2,%3}, [%4];"
        : "=r"(r[0]), "=r"(r[1]), "=r"(r[2]), "=r"(r[3]) : "r"(addr));
}
__device__ __forceinline__ void mma16816(float* d, const uint32_t* a, uint32_t b0, uint32_t b1) {
    asm volatile(
        "mma.sync.aligned.m16n8k16.row.col.f32.bf16.bf16.f32 "
        "{%0,%1,%2,%3}, {%4,%5,%6,%7}, {%8,%9}, {%0,%1,%2,%3};"
        : "+f"(d[0]), "+f"(d[1]), "+f"(d[2]), "+f"(d[3])
        : "r"(a[0]), "r"(a[1]), "r"(a[2]), "r"(a[3]), "r"(b0), "r"(b1));
}

// ---------------- prep: reorder + bf16-split weights ----------------
__global__ void prep_w(const float* __restrict__ Wih, const float* __restrict__ Whh,
                       const float* __restrict__ bih, const float* __restrict__ bhh,
                       int dec)
{
    __nv_bfloat16* Bh = dec ? g_Bh_dec : g_Bh_enc;
    __nv_bfloat16* Bl = dec ? g_Bl_dec : g_Bl_enc;
    float* br = dec ? g_br_dec : g_br_enc;
    const int total = GG * KTOT;
    for (int idx = blockIdx.x * blockDim.x + threadIdx.x; idx < total;
         idx += gridDim.x * blockDim.x) {
        int r = idx / KTOT, k = idx - r * KTOT;
        int j = r >> 2, gg = r & 3;
        int srow = gg * HH + j;
        float w = (k < FF) ? Wih[srow * FF + k] : Whh[(size_t)srow * HH + (k - FF)];
        __nv_bfloat16 hi, lo;
        bf16split(w, hi, lo);
        Bh[idx] = hi; Bl[idx] = lo;
    }
    for (int r = blockIdx.x * blockDim.x + threadIdx.x; r < GG;
         r += gridDim.x * blockDim.x) {
        int j = r >> 2, gg = r & 3;
        br[r] = bih[gg * HH + j] + bhh[gg * HH + j];
    }
}

// convert encoder inputs [b][t][f] -> [t][b][f] bf16 hi/lo
__global__ void prep_x(const float* __restrict__ x)
{
    const int total = SS * BB * FF;
    for (int idx = blockIdx.x * blockDim.x + threadIdx.x; idx < total;
         idx += gridDim.x * blockDim.x) {
        int t = idx / (BB * FF);
        int rem = idx - t * (BB * FF);
        int b = rem / FF, f = rem - b * FF;
        float v = x[(size_t)b * SS * FF + (size_t)t * FF + f];
        __nv_bfloat16 hi, lo;
        bf16split(v, hi, lo);
        g_Xh[idx] = hi; g_Xl[idx] = lo;
    }
}

__global__ void zero_kernel()
{
    for (int i = blockIdx.x * blockDim.x + threadIdx.x; i < BB * HH;
         i += gridDim.x * blockDim.x) {
        g_Hh[0][i] = __float2bfloat16_rn(0.f);
        g_Hl[0][i] = __float2bfloat16_rn(0.f);
        g_c[i] = 0.f;
    }
}

// ---------------- fused HMMA LSTM step ----------------
// D[256 x 4096] = [x|h] @ Wr^T via K'=3264 bf16-split GEMM + fused LSTM epilogue.
// grid (GG/BN=64, BB/BM=2), 256 threads (8 warps, 4M x 2N), warp tile 32x32.
// xsel: 0 = encoder x[t], 1 = last encoder x, 2 = decoder feedback
__global__ __launch_bounds__(256, 1)
void lstm_step(int xsel, int t, int dec, int pp)
{
    extern __shared__ __align__(128) char smem[];
    const uint32_t sb = smem_u32(smem);
    const int tid  = threadIdx.x;
    const int lane = tid & 31;
    const int wid  = tid >> 5;
    const int wm   = wid & 3;          // 0..3 (M)
    const int wn   = wid >> 2;         // 0..1 (N)
    const int n0   = blockIdx.x * BN;
    const int m0   = blockIdx.y * BM;

    const __nv_bfloat16* __restrict__ Bh = dec ? g_Bh_dec : g_Bh_enc;
    const __nv_bfloat16* __restrict__ Bl = dec ? g_Bl_dec : g_Bl_enc;
    const float* __restrict__ br = dec ? g_br_dec : g_br_enc;

    const __nv_bfloat16* __restrict__ xh;
    const __nv_bfloat16* __restrict__ xl;
    if (xsel == 2) { xh = g_Dxh; xl = g_Dxl; }
    else {
        int tt = (xsel == 1) ? (SS - 1) : t;
        xh = g_Xh + (size_t)tt * BB * FF;
        xl = g_Xl + (size_t)tt * BB * FF;
    }
    const __nv_bfloat16* __restrict__ hh = g_Hh[pp];
    const __nv_bfloat16* __restrict__ hl = g_Hl[pp];

    // loader: chunk c of K'=3264 into stage s. seg = c/17 selects split product.
    auto load_chunk = [&](int c, int s) {
        const int seg = c / 17, cc = c - seg * 17;
        const bool hi = (seg < 2);
        const __nv_bfloat16* asrc; int astr, akoff;
        if (cc == 0) { asrc = hi ? xh : xl; astr = FF; akoff = 0; }
        else         { asrc = hi ? hh : hl; astr = HH; akoff = (cc - 1) * KC; }
        const __nv_bfloat16* bsrc = (seg == 1) ? Bl : Bh;
        const int bkoff = cc * KC;
        const uint32_t abase = sb + s * STG_BYTES;
        const uint32_t bbase = abase + 16384;
#pragma unroll
        for (int i = 0; i < 4; i++) {            // A: 128 rows x 8 x 16B
            int idx = tid + i * 256;
            int row = idx >> 3, q = idx & 7;
            uint32_t dst = abase + row * 128 + ((q ^ (row & 7)) << 4);
            cp16(dst, asrc + (size_t)(m0 + row) * astr + akoff + q * 8);
        }
#pragma unroll
        for (int i = 0; i < 2; i++) {            // B: 64 rows x 8 x 16B
            int idx = tid + i * 256;
            int row = idx >> 3, q = idx & 7;
            uint32_t dst = bbase + row * 128 + ((q ^ (row & 7)) << 4);
            cp16(dst, bsrc + (size_t)(n0 + row) * KTOT + bkoff + q * 8);
        }
        cp_commit();
    };

    float acc[2][4][4];
#pragma unroll
    for (int mt = 0; mt < 2; mt++)
#pragma unroll
        for (int nt = 0; nt < 4; nt++)
#pragma unroll
            for (int i = 0; i < 4; i++) acc[mt][nt][i] = 0.f;

    // per-lane ldmatrix row indices (same formula for A and B tiles)
    const int lr = lane & 15, lh = lane >> 4;
    const int rA0 = wm * 32 + lr, rA1 = rA0 + 16;
    const int rB0 = wn * 32 + lr, rB1 = rB0 + 16;

    load_chunk(0, 0);
    load_chunk(1, 1);

    for (int c = 0; c < NCH; c++) {
        const int s = c % 3;
        if (c >= NCH - 2) cp_wait0(); else cp_wait1();
        __syncthreads();
        if (c + 2 < NCH) load_chunk(c + 2, (c + 2) % 3);

        const uint32_t abase = sb + s * STG_BYTES;
        const uint32_t bbase = abase + 16384;
#pragma unroll
        for (int ks = 0; ks < 4; ks++) {
            const int qk = (ks << 1) | lh;
            uint32_t a0[4], a1[4], b0[4], b1[4];
            ldsm4(a0, abase + rA0 * 128 + ((qk ^ (rA0 & 7)) << 4));
            ldsm4(a1, abase + rA1 * 128 + ((qk ^ (rA1 & 7)) << 4));
            ldsm4(b0, bbase + rB0 * 128 + ((qk ^ (rB0 & 7)) << 4));
            ldsm4(b1, bbase + rB1 * 128 + ((qk ^ (rB1 & 7)) << 4));
            // b0 covers n-tiles 0,1 ; b1 covers n-tiles 2,3
            mma16816(acc[0][0], a0, b0[0], b0[2]);
            mma16816(acc[0][1], a0, b0[1], b0[3]);
            mma16816(acc[0][2], a0, b1[0], b1[2]);
            mma16816(acc[0][3], a0, b1[1], b1[3]);
            mma16816(acc[1][0], a1, b0[0], b0[2]);
            mma16816(acc[1][1], a1, b0[1], b0[3]);
            mma16816(acc[1][2], a1, b1[0], b1[2]);
            mma16816(acc[1][3], a1, b1[1], b1[3]);
        }
    }

    // ---------------- fused LSTM epilogue ----------------
    // lane holds col pairs {2c2, 2c2+1} in each 8-wide n-tile; one shfl_xor(1)
    // assembles full (i,f,g,o) quads. even c2 -> rows l>>2, odd c2 -> +8.
    const int c2 = lane & 3;
    const bool even = !(c2 & 1);
    const int rbase = lane >> 2;
    __nv_bfloat16* __restrict__ hho = g_Hh[pp ^ 1];
    __nv_bfloat16* __restrict__ hlo = g_Hl[pp ^ 1];

#pragma unroll
    for (int mt = 0; mt < 2; mt++) {
#pragma unroll
        for (int nt = 0; nt < 4; nt++) {
            float* d = acc[mt][nt];
            float s0 = __shfl_xor_sync(0xFFFFFFFFu, d[0], 1);
            float s1 = __shfl_xor_sync(0xFFFFFFFFu, d[1], 1);
            float s2 = __shfl_xor_sync(0xFFFFFFFFu, d[2], 1);
            float s3 = __shfl_xor_sync(0xFFFFFFFFu, d[3], 1);
            float q0, q1, q2, q3; int r;
            if (even) { q0 = d[0]; q1 = d[1]; q2 = s0; q3 = s1; r = rbase; }
            else      { q0 = s2; q1 = s3; q2 = d[2]; q3 = d[3]; r = rbase + 8; }
            const int n = n0 + wn * 32 + nt * 8 + (c2 >> 1) * 4;  // gate-row base (j*4)
            const int j = n >> 2;
            const int b = m0 + wm * 32 + mt * 16 + r;
            const float4 bb4 = *reinterpret_cast<const float4*>(br + n);
            float iv = sigf(q0 + bb4.x);
            float fv = sigf(q1 + bb4.y);
            float gv = tanhf_(q2 + bb4.z);
            float ov = sigf(q3 + bb4.w);
            const int o = b * HH + j;
            float cn = fv * g_c[o] + iv * gv;
            g_c[o] = cn;
            float hn = ov * tanhf_(cn);
            g_hf[o] = hn;
            __nv_bfloat16 hi, lo;
            bf16split(hn, hi, lo);
            hho[o] = hi; hlo[o] = lo;
        }
    }
}

// ---------------- fc: pred = h @ W_fc^T + b_fc ----------------
__global__ __launch_bounds__(64)
void fc_kernel(const float* __restrict__ Wfc, const float* __restrict__ bfc,
               float* __restrict__ out, int t)
{
    int b = blockIdx.x;
    const float* h = g_hf + (size_t)b * HH;
    __shared__ __align__(16) float hs[HH];
    for (int i = threadIdx.x; i < HH / 4; i += 64)
        reinterpret_cast<float4*>(hs)[i] = reinterpret_cast<const float4*>(h)[i];
    __syncthreads();

    int f = threadIdx.x;
    float s = bfc[f];
    const float4* w4 = reinterpret_cast<const float4*>(Wfc + (size_t)f * HH);
    const float4* h4 = reinterpret_cast<const float4*>(hs);
#pragma unroll 4
    for (int k = 0; k < HH / 4; k++) {
        float4 wv = w4[k], hv = h4[k];
        s += wv.x * hv.x + wv.y * hv.y + wv.z * hv.z + wv.w * hv.w;
    }
    __nv_bfloat16 hi, lo;
    bf16split(s, hi, lo);
    g_Dxh[b * FF + f] = hi;
    g_Dxl[b * FF + f] = lo;
    out[(size_t)b * TT * FF + (size_t)t * FF + f] = s;
}

// ---------------- launch ----------------
extern "C" void kernel_launch(void* const* d_in, const int* in_sizes, int n_in,
                              void* d_out, int out_size)
{
    const float* x     = (const float*)d_in[0];
    const float* Wih_e = (const float*)d_in[1];
    const float* Whh_e = (const float*)d_in[2];
    const float* bih_e = (const float*)d_in[3];
    const float* bhh_e = (const float*)d_in[4];
    const float* Wih_d = (const float*)d_in[5];
    const float* Whh_d = (const float*)d_in[6];
    const float* bih_d = (const float*)d_in[7];
    const float* bhh_d = (const float*)d_in[8];
    const float* Wfc   = (const float*)d_in[9];
    const float* bfc   = (const float*)d_in[10];
    float* out = (float*)d_out;

    static int smem_set = 0;
    if (!smem_set) {
        cudaFuncSetAttribute(lstm_step, cudaFuncAttributeMaxDynamicSharedMemorySize, SMEM_BYTES);
        smem_set = 1;
    }

    prep_w<<<1024, 256>>>(Wih_e, Whh_e, bih_e, bhh_e, 0);
    prep_w<<<1024, 256>>>(Wih_d, Whh_d, bih_d, bhh_d, 1);
    prep_x<<<1024, 256>>>(x);
    zero_kernel<<<512, 256>>>();

    dim3 grid(GG / BN, BB / BM);   // (64, 2)
    int pp = 0;
    for (int t = 0; t < SS; t++) {
        lstm_step<<<grid, 256, SMEM_BYTES>>>(0, t, 0, pp);
        pp ^= 1;
    }
    for (int t = 0; t < TT; t++) {
        lstm_step<<<grid, 256, SMEM_BYTES>>>((t == 0) ? 1 : 2, 0, 1, pp);
        pp ^= 1;
        fc_kernel<<<BB, 64>>>(Wfc, bfc, out, t);
    }
}

// round 7
// speedup vs baseline: 2.1970x; 1.2903x over previous
#include <cuda_runtime.h>
#include <cuda_bf16.h>
#include <cstdint>
#include <cstddef>

// Problem constants
#define BB 256      // batch
#define SS 512      // encoder sequence length
#define FF 64       // feature dim
#define HH 1024     // hidden dim
#define GG 4096     // 4*H gate rows
#define KTOT 1088   // F + H
#define TT 64       // prediction length
#define NSTEP (SS + TT)

// GEMM tiling: 17 chunks of K=64; each chunk holds Ah/Al/Bh/Bl (3 split products)
#define KC 64
#define NCH 17
#define BM 128
#define BN 64
#define STG 49152                      // Ah 16K + Al 16K + Bh 8K + Bl 8K
#define FC_OFF (3 * STG)               // 8KB fc scratch after the 3 stages
#define SMEM_BYTES (FC_OFF + 8192)

// ---------------- device globals ----------------
__device__ __align__(16) __nv_bfloat16 g_Bh_enc[GG * KTOT];  // weights hi, rows j*4+g, K-major
__device__ __align__(16) __nv_bfloat16 g_Bl_enc[GG * KTOT];  // weights lo
__device__ __align__(16) __nv_bfloat16 g_Bh_dec[GG * KTOT];
__device__ __align__(16) __nv_bfloat16 g_Bl_dec[GG * KTOT];
__device__ __align__(16) float g_br_enc[GG];                 // combined bias, reordered
__device__ __align__(16) float g_br_dec[GG];
__device__ __align__(16) __nv_bfloat16 g_Xh[SS * BB * FF];   // encoder x, [t][b][f], hi
__device__ __align__(16) __nv_bfloat16 g_Xl[SS * BB * FF];
__device__ __align__(16) __nv_bfloat16 g_Hh[2][BB * HH];     // hidden state hi (ping-pong)
__device__ __align__(16) __nv_bfloat16 g_Hl[2][BB * HH];
__device__ __align__(16) __nv_bfloat16 g_Dxh[BB * FF];       // decoder feedback x hi
__device__ __align__(16) __nv_bfloat16 g_Dxl[BB * FF];
__device__ float g_c[BB * HH];                               // cell state (in-place, CTA-local)
__device__ float g_hf[BB * HH];                              // fp32 hidden (for fc)
__device__ unsigned g_bar;                                   // grid barrier counter

// ---------------- helpers ----------------
__device__ __forceinline__ uint32_t smem_u32(const void* p) {
    return (uint32_t)__cvta_generic_to_shared(p);
}
// L2-only (bypass L1): activations change across steps; L1 is NOT flushed inside
// a persistent kernel, so h/x loads must not be L1-cached.
__device__ __forceinline__ void cp16cg(uint32_t dst, const void* src) {
    asm volatile("cp.async.cg.shared.global [%0], [%1], 16;\n" :: "r"(dst), "l"(src));
}
// L1-cached: immutable weights
__device__ __forceinline__ void cp16ca(uint32_t dst, const void* src) {
    asm volatile("cp.async.ca.shared.global [%0], [%1], 16;\n" :: "r"(dst), "l"(src));
}
__device__ __forceinline__ void cp_commit() { asm volatile("cp.async.commit_group;\n"); }
__device__ __forceinline__ void cp_wait0()  { asm volatile("cp.async.wait_group 0;\n" ::: "memory"); }
__device__ __forceinline__ void cp_wait1()  { asm volatile("cp.async.wait_group 1;\n" ::: "memory"); }

__device__ __forceinline__ float sigf(float x)   { return 1.f / (1.f + __expf(-x)); }
__device__ __forceinline__ float tanhf_(float x) { return 2.f / (1.f + __expf(-2.f * x)) - 1.f; }

__device__ __forceinline__ void bf16split(float v, __nv_bfloat16& hi, __nv_bfloat16& lo) {
    hi = __float2bfloat16_rn(v);
    lo = __float2bfloat16_rn(v - __bfloat162float(hi));
}

__device__ __forceinline__ void ldsm4(uint32_t* r, uint32_t addr) {
    asm volatile("ldmatrix.sync.aligned.m8n8.x4.shared.b16 {%0,%1,%2,%3}, [%4];"
        : "=r"(r[0]), "=r"(r[1]), "=r"(r[2]), "=r"(r[3]) : "r"(addr));
}
__device__ __forceinline__ void mma16816(float* d, const uint32_t* a, uint32_t b0, uint32_t b1) {
    asm volatile(
        "mma.sync.aligned.m16n8k16.row.col.f32.bf16.bf16.f32 "
        "{%0,%1,%2,%3}, {%4,%5,%6,%7}, {%8,%9}, {%0,%1,%2,%3};"
        : "+f"(d[0]), "+f"(d[1]), "+f"(d[2]), "+f"(d[3])
        : "r"(a[0]), "r"(a[1]), "r"(a[2]), "r"(a[3]), "r"(b0), "r"(b1));
}

// grid barrier: 128 CTAs, all resident (grid 128 <= 148 SMs, occ 1 -> single wave)
__device__ __forceinline__ void grid_barrier(unsigned target) {
    __threadfence();
    __syncthreads();
    if (threadIdx.x == 0) {
        atomicAdd(&g_bar, 1u);
        while (*(volatile unsigned*)&g_bar < target) __nanosleep(64);
    }
    __syncthreads();
    __threadfence();
}

// ---------------- prep kernels ----------------
__global__ void prep_w(const float* __restrict__ Wih, const float* __restrict__ Whh,
                       const float* __restrict__ bih, const float* __restrict__ bhh,
                       int dec)
{
    __nv_bfloat16* Bh = dec ? g_Bh_dec : g_Bh_enc;
    __nv_bfloat16* Bl = dec ? g_Bl_dec : g_Bl_enc;
    float* br = dec ? g_br_dec : g_br_enc;
    const int total = GG * KTOT;
    for (int idx = blockIdx.x * blockDim.x + threadIdx.x; idx < total;
         idx += gridDim.x * blockDim.x) {
        int r = idx / KTOT, k = idx - r * KTOT;
        int j = r >> 2, gg = r & 3;
        int srow = gg * HH + j;
        float w = (k < FF) ? Wih[srow * FF + k] : Whh[(size_t)srow * HH + (k - FF)];
        __nv_bfloat16 hi, lo;
        bf16split(w, hi, lo);
        Bh[idx] = hi; Bl[idx] = lo;
    }
    for (int r = blockIdx.x * blockDim.x + threadIdx.x; r < GG;
         r += gridDim.x * blockDim.x) {
        int j = r >> 2, gg = r & 3;
        br[r] = bih[gg * HH + j] + bhh[gg * HH + j];
    }
}

__global__ void prep_x(const float* __restrict__ x)
{
    const int total = SS * BB * FF;
    for (int idx = blockIdx.x * blockDim.x + threadIdx.x; idx < total;
         idx += gridDim.x * blockDim.x) {
        int t = idx / (BB * FF);
        int rem = idx - t * (BB * FF);
        int b = rem / FF, f = rem - b * FF;
        float v = x[(size_t)b * SS * FF + (size_t)t * FF + f];
        __nv_bfloat16 hi, lo;
        bf16split(v, hi, lo);
        g_Xh[idx] = hi; g_Xl[idx] = lo;
    }
}

__global__ void zero_kernel()
{
    if (blockIdx.x == 0 && threadIdx.x == 0) g_bar = 0;
    for (int i = blockIdx.x * blockDim.x + threadIdx.x; i < BB * HH;
         i += gridDim.x * blockDim.x) {
        g_Hh[0][i] = __float2bfloat16_rn(0.f);
        g_Hl[0][i] = __float2bfloat16_rn(0.f);
        g_c[i] = 0.f;
    }
}

// ---------------- persistent fused LSTM (all 576 steps + decoder fc) ----------------
// grid (GG/BN=64, BB/BM=2) = 128 CTAs, 256 threads (8 warps, 4M x 2N), warp tile 32x32.
__global__ __launch_bounds__(256, 1)
void lstm_persistent(const float* __restrict__ Wfc, const float* __restrict__ bfc,
                     float* __restrict__ out)
{
    extern __shared__ __align__(128) char smem[];
    const uint32_t sb = smem_u32(smem);
    const int tid  = threadIdx.x;
    const int lane = tid & 31;
    const int wid  = tid >> 5;
    const int wm   = wid & 3;          // 0..3 (M)
    const int wn   = wid >> 2;         // 0..1 (N)
    const int n0   = blockIdx.x * BN;
    const int m0   = blockIdx.y * BM;
    const int cta  = blockIdx.y * 64 + blockIdx.x;

    const int lr = lane & 15, lh = lane >> 4;
    const int rA0 = wm * 32 + lr, rA1 = rA0 + 16;
    const int rB0 = wn * 32 + lr, rB1 = rB0 + 16;
    const int c2 = lane & 3;
    const bool evenlane = !(c2 & 1);
    const int rbase = lane >> 2;

    unsigned epoch = 0;
    bool preloaded = false;

    for (int step = 0; step < NSTEP; step++) {
        const bool dec = (step >= SS);
        const int pp = step & 1;
        const __nv_bfloat16* __restrict__ Bh = dec ? g_Bh_dec : g_Bh_enc;
        const __nv_bfloat16* __restrict__ Bl = dec ? g_Bl_dec : g_Bl_enc;
        const float* __restrict__ br = dec ? g_br_dec : g_br_enc;
        const __nv_bfloat16* __restrict__ xh;
        const __nv_bfloat16* __restrict__ xl;
        if (step < SS)      { xh = g_Xh + (size_t)step * BB * FF;     xl = g_Xl + (size_t)step * BB * FF; }
        else if (step == SS){ xh = g_Xh + (size_t)(SS - 1) * BB * FF; xl = g_Xl + (size_t)(SS - 1) * BB * FF; }
        else                { xh = g_Dxh; xl = g_Dxl; }
        const __nv_bfloat16* __restrict__ hh = g_Hh[pp];
        const __nv_bfloat16* __restrict__ hl = g_Hl[pp];

        // chunk c: Ah/Al/Bh/Bl for K slice [c*64, c*64+64)
        auto load_chunk = [&](int c, int s,
                              const __nv_bfloat16* xh_, const __nv_bfloat16* xl_,
                              const __nv_bfloat16* Bh_, const __nv_bfloat16* Bl_) {
            const __nv_bfloat16 *ah, *al; int astr, ak;
            if (c == 0) { ah = xh_; al = xl_; astr = FF; ak = 0; }
            else        { ah = hh;  al = hl;  astr = HH; ak = (c - 1) * KC; }
            const int bk = c * KC;
            const uint32_t base = sb + s * STG;
#pragma unroll
            for (int i = 0; i < 4; i++) {          // A: 128 rows x 8 segs
                int idx = tid + i * 256;
                int row = idx >> 3, q = idx & 7;
                uint32_t sw = (uint32_t)(row * 128) + ((q ^ (row & 7)) << 4);
                const size_t ao = (size_t)(m0 + row) * astr + ak + q * 8;
                cp16cg(base + sw, ah + ao);
                cp16cg(base + 16384 + sw, al + ao);
            }
#pragma unroll
            for (int i = 0; i < 2; i++) {          // B: 64 rows x 8 segs
                int idx = tid + i * 256;
                int row = idx >> 3, q = idx & 7;
                uint32_t sw = (uint32_t)(row * 128) + ((q ^ (row & 7)) << 4);
                const size_t bo = (size_t)(n0 + row) * KTOT + bk + q * 8;
                cp16ca(base + 32768 + sw, Bh_ + bo);
                cp16ca(base + 40960 + sw, Bl_ + bo);
            }
            cp_commit();
        };

        float acc[2][4][4];
#pragma unroll
        for (int mt = 0; mt < 2; mt++)
#pragma unroll
            for (int nt = 0; nt < 4; nt++)
#pragma unroll
                for (int i = 0; i < 4; i++) acc[mt][nt][i] = 0.f;

        if (!preloaded) load_chunk(0, 0, xh, xl, Bh, Bl);
        preloaded = false;
        load_chunk(1, 1, xh, xl, Bh, Bl);

        for (int c = 0; c < NCH; c++) {
            const int s = c % 3;
            if (c >= NCH - 2) cp_wait0(); else cp_wait1();
            __syncthreads();
            if (c + 2 < NCH) load_chunk(c + 2, (c + 2) % 3, xh, xl, Bh, Bl);

            const uint32_t ahb = sb + s * STG;
            const uint32_t alb = ahb + 16384;
            const uint32_t bhb = ahb + 32768;
            const uint32_t blb = ahb + 40960;
#pragma unroll
            for (int ks = 0; ks < 4; ks++) {
                const int qk = (ks << 1) | lh;
                uint32_t ah0[4], ah1[4], al0[4], al1[4];
                uint32_t bh0[4], bh1[4], bl0[4], bl1[4];
                ldsm4(ah0, ahb + rA0 * 128 + ((qk ^ (rA0 & 7)) << 4));
                ldsm4(ah1, ahb + rA1 * 128 + ((qk ^ (rA1 & 7)) << 4));
                ldsm4(bh0, bhb + rB0 * 128 + ((qk ^ (rB0 & 7)) << 4));
                ldsm4(bh1, bhb + rB1 * 128 + ((qk ^ (rB1 & 7)) << 4));
                ldsm4(al0, alb + rA0 * 128 + ((qk ^ (rA0 & 7)) << 4));
                ldsm4(al1, alb + rA1 * 128 + ((qk ^ (rA1 & 7)) << 4));
                ldsm4(bl0, blb + rB0 * 128 + ((qk ^ (rB0 & 7)) << 4));
                ldsm4(bl1, blb + rB1 * 128 + ((qk ^ (rB1 & 7)) << 4));
                // Ah * Bh
                mma16816(acc[0][0], ah0, bh0[0], bh0[2]);
                mma16816(acc[0][1], ah0, bh0[1], bh0[3]);
                mma16816(acc[0][2], ah0, bh1[0], bh1[2]);
                mma16816(acc[0][3], ah0, bh1[1], bh1[3]);
                mma16816(acc[1][0], ah1, bh0[0], bh0[2]);
                mma16816(acc[1][1], ah1, bh0[1], bh0[3]);
                mma16816(acc[1][2], ah1, bh1[0], bh1[2]);
                mma16816(acc[1][3], ah1, bh1[1], bh1[3]);
                // Ah * Bl
                mma16816(acc[0][0], ah0, bl0[0], bl0[2]);
                mma16816(acc[0][1], ah0, bl0[1], bl0[3]);
                mma16816(acc[0][2], ah0, bl1[0], bl1[2]);
                mma16816(acc[0][3], ah0, bl1[1], bl1[3]);
                mma16816(acc[1][0], ah1, bl0[0], bl0[2]);
                mma16816(acc[1][1], ah1, bl0[1], bl0[3]);
                mma16816(acc[1][2], ah1, bl1[0], bl1[2]);
                mma16816(acc[1][3], ah1, bl1[1], bl1[3]);
                // Al * Bh
                mma16816(acc[0][0], al0, bh0[0], bh0[2]);
                mma16816(acc[0][1], al0, bh0[1], bh0[3]);
                mma16816(acc[0][2], al0, bh1[0], bh1[2]);
                mma16816(acc[0][3], al0, bh1[1], bh1[3]);
                mma16816(acc[1][0], al1, bh0[0], bh0[2]);
                mma16816(acc[1][1], al1, bh0[1], bh0[3]);
                mma16816(acc[1][2], al1, bh1[0], bh1[2]);
                mma16816(acc[1][3], al1, bh1[1], bh1[3]);
            }
        }

        // ---------------- fused LSTM epilogue (same mapping as R5) ----------------
        {
            __nv_bfloat16* __restrict__ hho = g_Hh[pp ^ 1];
            __nv_bfloat16* __restrict__ hlo = g_Hl[pp ^ 1];
#pragma unroll
            for (int mt = 0; mt < 2; mt++) {
#pragma unroll
                for (int nt = 0; nt < 4; nt++) {
                    float* d = acc[mt][nt];
                    float s0 = __shfl_xor_sync(0xFFFFFFFFu, d[0], 1);
                    float s1 = __shfl_xor_sync(0xFFFFFFFFu, d[1], 1);
                    float s2 = __shfl_xor_sync(0xFFFFFFFFu, d[2], 1);
                    float s3 = __shfl_xor_sync(0xFFFFFFFFu, d[3], 1);
                    float q0, q1, q2, q3; int r;
                    if (evenlane) { q0 = d[0]; q1 = d[1]; q2 = s0; q3 = s1; r = rbase; }
                    else          { q0 = s2; q1 = s3; q2 = d[2]; q3 = d[3]; r = rbase + 8; }
                    const int n = n0 + wn * 32 + nt * 8 + (c2 >> 1) * 4;  // gate base (j*4)
                    const int j = n >> 2;
                    const int b = m0 + wm * 32 + mt * 16 + r;
                    const float4 bb4 = *reinterpret_cast<const float4*>(br + n);
                    float iv = sigf(q0 + bb4.x);
                    float fv = sigf(q1 + bb4.y);
                    float gv = tanhf_(q2 + bb4.z);
                    float ov = sigf(q3 + bb4.w);
                    const int o = b * HH + j;
                    float cn = fv * g_c[o] + iv * gv;
                    g_c[o] = cn;
                    float hn = ov * tanhf_(cn);
                    g_hf[o] = hn;
                    __nv_bfloat16 hi, lo;
                    bf16split(hn, hi, lo);
                    hho[o] = hi; hlo[o] = lo;
                }
            }
        }

        // preload next step's x-chunk (independent of new h) to overlap the barrier
        if (step + 1 < NSTEP && step + 1 <= SS) {
            const __nv_bfloat16* nxh;
            const __nv_bfloat16* nxl;
            if (step + 1 < SS) { nxh = g_Xh + (size_t)(step + 1) * BB * FF;
                                 nxl = g_Xl + (size_t)(step + 1) * BB * FF; }
            else               { nxh = g_Xh + (size_t)(SS - 1) * BB * FF;
                                 nxl = g_Xl + (size_t)(SS - 1) * BB * FF; }
            const __nv_bfloat16* nBh = (step + 1 >= SS) ? g_Bh_dec : g_Bh_enc;
            const __nv_bfloat16* nBl = (step + 1 >= SS) ? g_Bl_dec : g_Bl_enc;
            load_chunk(0, 0, nxh, nxl, nBh, nBl);
            preloaded = true;
        }

        epoch++;
        grid_barrier(128u * epoch);

        if (dec) {
            // ---------------- fc phase: pred = h @ Wfc^T + bfc ----------------
            const int tdec = step - SS;
            float* fcb = reinterpret_cast<float*>(smem + FC_OFF);
            const int b0 = cta * 2;
            for (int i = tid; i < 2 * (HH / 4); i += 256) {
                int rrow = i / (HH / 4), o = i % (HH / 4);
                float4 v = __ldcg(reinterpret_cast<const float4*>(
                    g_hf + (size_t)(b0 + rrow) * HH) + o);
                reinterpret_cast<float4*>(fcb)[i] = v;
            }
            __syncthreads();
            if (tid < 128) {
                int bl_ = tid >> 6, f = tid & 63;
                const float4* w4 = reinterpret_cast<const float4*>(Wfc + (size_t)f * HH);
                const float4* h4 = reinterpret_cast<const float4*>(fcb + bl_ * HH);
                float s = bfc[f];
#pragma unroll 4
                for (int k = 0; k < HH / 4; k++) {
                    float4 wv = w4[k], hv = h4[k];
                    s += wv.x * hv.x + wv.y * hv.y + wv.z * hv.z + wv.w * hv.w;
                }
                int b = b0 + bl_;
                __nv_bfloat16 hi, lo;
                bf16split(s, hi, lo);
                g_Dxh[b * FF + f] = hi;
                g_Dxl[b * FF + f] = lo;
                out[(size_t)b * TT * FF + (size_t)tdec * FF + f] = s;
            }
            epoch++;
            grid_barrier(128u * epoch);
        }
    }
}

// ---------------- launch ----------------
extern "C" void kernel_launch(void* const* d_in, const int* in_sizes, int n_in,
                              void* d_out, int out_size)
{
    const float* x     = (const float*)d_in[0];
    const float* Wih_e = (const float*)d_in[1];
    const float* Whh_e = (const float*)d_in[2];
    const float* bih_e = (const float*)d_in[3];
    const float* bhh_e = (const float*)d_in[4];
    const float* Wih_d = (const float*)d_in[5];
    const float* Whh_d = (const float*)d_in[6];
    const float* bih_d = (const float*)d_in[7];
    const float* bhh_d = (const float*)d_in[8];
    const float* Wfc   = (const float*)d_in[9];
    const float* bfc   = (const float*)d_in[10];
    float* out = (float*)d_out;

    cudaFuncSetAttribute(lstm_persistent, cudaFuncAttributeMaxDynamicSharedMemorySize, SMEM_BYTES);

    prep_w<<<1024, 256>>>(Wih_e, Whh_e, bih_e, bhh_e, 0);
    prep_w<<<1024, 256>>>(Wih_d, Whh_d, bih_d, bhh_d, 1);
    prep_x<<<1024, 256>>>(x);
    zero_kernel<<<512, 256>>>();

    dim3 grid(GG / BN, BB / BM);   // (64, 2) = 128 CTAs, one wave
    lstm_persistent<<<grid, 256, SMEM_BYTES>>>(Wfc, bfc, out);
}

// round 8
// speedup vs baseline: 2.7695x; 1.2605x over previous
#include <cuda_runtime.h>
#include <cuda_fp16.h>
#include <cstdint>
#include <cstddef>

// Problem constants
#define BB 256      // batch
#define SS 512      // encoder sequence length
#define FF 64       // feature dim
#define HH 1024     // hidden dim
#define GG 4096     // 4*H gate rows
#define KTOT 1088   // F + H
#define TT 64       // prediction length
#define NSTEP (SS + TT)

// GEMM tiling: 17 chunks of K=64; each chunk holds A / Bh / Bl (2 split products)
#define KC 64
#define NCH 17
#define BM 128
#define BN 64
#define STG 32768                      // A 16K + Bh 8K + Bl 8K
#define FC_OFF (3 * STG)               // 8KB fc scratch after the 3 stages
#define SMEM_BYTES (FC_OFF + 8192)

// ---------------- device globals ----------------
__device__ __align__(16) __half g_Bh_enc[GG * KTOT];  // weights hi fp16, rows j*4+g, K-major
__device__ __align__(16) __half g_Bl_enc[GG * KTOT];  // weights lo fp16
__device__ __align__(16) __half g_Bh_dec[GG * KTOT];
__device__ __align__(16) __half g_Bl_dec[GG * KTOT];
__device__ __align__(16) float g_br_enc[GG];          // combined bias, reordered
__device__ __align__(16) float g_br_dec[GG];
__device__ __align__(16) __half g_X[SS * BB * FF];    // encoder x, [t][b][f], fp16
__device__ __align__(16) __half g_H[2][BB * HH];      // hidden state fp16 (ping-pong)
__device__ __align__(16) __half g_Dx[BB * FF];        // decoder feedback x fp16
__device__ float g_c[BB * HH];                        // cell state (in-place, CTA-local)
__device__ float g_hf[BB * HH];                       // fp32 hidden (for fc)
__device__ unsigned g_bar;                            // grid barrier counter

// ---------------- helpers ----------------
__device__ __forceinline__ uint32_t smem_u32(const void* p) {
    return (uint32_t)__cvta_generic_to_shared(p);
}
// L2-only (bypass L1): activations change across steps; L1 is NOT flushed inside
// a persistent kernel, so h/x loads must not be L1-cached.
__device__ __forceinline__ void cp16cg(uint32_t dst, const void* src) {
    asm volatile("cp.async.cg.shared.global [%0], [%1], 16;\n" :: "r"(dst), "l"(src));
}
// L1-cached: immutable weights
__device__ __forceinline__ void cp16ca(uint32_t dst, const void* src) {
    asm volatile("cp.async.ca.shared.global [%0], [%1], 16;\n" :: "r"(dst), "l"(src));
}
__device__ __forceinline__ void cp_commit() { asm volatile("cp.async.commit_group;\n"); }
__device__ __forceinline__ void cp_wait0()  { asm volatile("cp.async.wait_group 0;\n" ::: "memory"); }
__device__ __forceinline__ void cp_wait1()  { asm volatile("cp.async.wait_group 1;\n" ::: "memory"); }

__device__ __forceinline__ float sigf(float x)   { return 1.f / (1.f + __expf(-x)); }
__device__ __forceinline__ float tanhf_(float x) { return 2.f / (1.f + __expf(-2.f * x)) - 1.f; }

__device__ __forceinline__ void ldsm4(uint32_t* r, uint32_t addr) {
    asm volatile("ldmatrix.sync.aligned.m8n8.x4.shared.b16 {%0,%1,%2,%3}, [%4];"
        : "=r"(r[0]), "=r"(r[1]), "=r"(r[2]), "=r"(r[3]) : "r"(addr));
}
__device__ __forceinline__ void mma16816(float* d, const uint32_t* a, uint32_t b0, uint32_t b1) {
    asm volatile(
        "mma.sync.aligned.m16n8k16.row.col.f32.f16.f16.f32 "
        "{%0,%1,%2,%3}, {%4,%5,%6,%7}, {%8,%9}, {%0,%1,%2,%3};"
        : "+f"(d[0]), "+f"(d[1]), "+f"(d[2]), "+f"(d[3])
        : "r"(a[0]), "r"(a[1]), "r"(a[2]), "r"(a[3]), "r"(b0), "r"(b1));
}

// grid barrier: 128 CTAs, all resident (grid 128 <= 148 SMs, occ 1 -> single wave)
__device__ __forceinline__ void grid_barrier(unsigned target) {
    __threadfence();
    __syncthreads();
    if (threadIdx.x == 0) {
        atomicAdd(&g_bar, 1u);
        while (*(volatile unsigned*)&g_bar < target) __nanosleep(64);
    }
    __syncthreads();
    __threadfence();
}

// ---------------- prep kernels ----------------
__global__ void prep_w(const float* __restrict__ Wih, const float* __restrict__ Whh,
                       const float* __restrict__ bih, const float* __restrict__ bhh,
                       int dec)
{
    __half* Bh = dec ? g_Bh_dec : g_Bh_enc;
    __half* Bl = dec ? g_Bl_dec : g_Bl_enc;
    float* br = dec ? g_br_dec : g_br_enc;
    const int total = GG * KTOT;
    for (int idx = blockIdx.x * blockDim.x + threadIdx.x; idx < total;
         idx += gridDim.x * blockDim.x) {
        int r = idx / KTOT, k = idx - r * KTOT;
        int j = r >> 2, gg = r & 3;
        int srow = gg * HH + j;
        float w = (k < FF) ? Wih[srow * FF + k] : Whh[(size_t)srow * HH + (k - FF)];
        __half hi = __float2half_rn(w);
        __half lo = __float2half_rn(w - __half2float(hi));
        Bh[idx] = hi; Bl[idx] = lo;
    }
    for (int r = blockIdx.x * blockDim.x + threadIdx.x; r < GG;
         r += gridDim.x * blockDim.x) {
        int j = r >> 2, gg = r & 3;
        br[r] = bih[gg * HH + j] + bhh[gg * HH + j];
    }
}

__global__ void prep_x(const float* __restrict__ x)
{
    const int total = SS * BB * FF;
    for (int idx = blockIdx.x * blockDim.x + threadIdx.x; idx < total;
         idx += gridDim.x * blockDim.x) {
        int t = idx / (BB * FF);
        int rem = idx - t * (BB * FF);
        int b = rem / FF, f = rem - b * FF;
        g_X[idx] = __float2half_rn(x[(size_t)b * SS * FF + (size_t)t * FF + f]);
    }
}

__global__ void zero_kernel()
{
    if (blockIdx.x == 0 && threadIdx.x == 0) g_bar = 0;
    for (int i = blockIdx.x * blockDim.x + threadIdx.x; i < BB * HH;
         i += gridDim.x * blockDim.x) {
        g_H[0][i] = __float2half_rn(0.f);
        g_c[i] = 0.f;
    }
}

// ---------------- persistent fused LSTM (all 576 steps + decoder fc) ----------------
// grid (GG/BN=64, BB/BM=2) = 128 CTAs, 256 threads (8 warps, 4M x 2N), warp tile 32x32.
// D = A(fp16) @ (Bh + Bl)^T  (2 MMA products), fused LSTM epilogue.
__global__ __launch_bounds__(256, 1)
void lstm_persistent(const float* __restrict__ Wfc, const float* __restrict__ bfc,
                     float* __restrict__ out)
{
    extern __shared__ __align__(128) char smem[];
    const uint32_t sb = smem_u32(smem);
    const int tid  = threadIdx.x;
    const int lane = tid & 31;
    const int wid  = tid >> 5;
    const int wm   = wid & 3;          // 0..3 (M)
    const int wn   = wid >> 2;         // 0..1 (N)
    const int n0   = blockIdx.x * BN;
    const int m0   = blockIdx.y * BM;
    const int cta  = blockIdx.y * 64 + blockIdx.x;

    const int lr = lane & 15, lh = lane >> 4;
    const int rA0 = wm * 32 + lr, rA1 = rA0 + 16;
    const int rB0 = wn * 32 + lr, rB1 = rB0 + 16;
    const int c2 = lane & 3;
    const bool evenlane = !(c2 & 1);
    const int rbase = lane >> 2;

    unsigned epoch = 0;
    bool preloaded = false;

    for (int step = 0; step < NSTEP; step++) {
        const bool dec = (step >= SS);
        const int pp = step & 1;
        const __half* __restrict__ Bh = dec ? g_Bh_dec : g_Bh_enc;
        const __half* __restrict__ Bl = dec ? g_Bl_dec : g_Bl_enc;
        const float* __restrict__ br = dec ? g_br_dec : g_br_enc;
        const __half* __restrict__ xp;
        if (step < SS)       xp = g_X + (size_t)step * BB * FF;
        else if (step == SS) xp = g_X + (size_t)(SS - 1) * BB * FF;
        else                 xp = g_Dx;
        const __half* __restrict__ hp = g_H[pp];

        // chunk c: A / Bh / Bl for K slice [c*64, c*64+64)
        auto load_chunk = [&](int c, int s, const __half* x_,
                              const __half* Bh_, const __half* Bl_) {
            const __half* ap; int astr, ak;
            if (c == 0) { ap = x_; astr = FF; ak = 0; }
            else        { ap = hp; astr = HH; ak = (c - 1) * KC; }
            const int bk = c * KC;
            const uint32_t base = sb + s * STG;
#pragma unroll
            for (int i = 0; i < 4; i++) {          // A: 128 rows x 8 segs of 16B
                int idx = tid + i * 256;
                int row = idx >> 3, q = idx & 7;
                uint32_t sw = (uint32_t)(row * 128) + ((q ^ (row & 7)) << 4);
                cp16cg(base + sw, ap + (size_t)(m0 + row) * astr + ak + q * 8);
            }
#pragma unroll
            for (int i = 0; i < 2; i++) {          // B: 64 rows x 8 segs (x2 buffers)
                int idx = tid + i * 256;
                int row = idx >> 3, q = idx & 7;
                uint32_t sw = (uint32_t)(row * 128) + ((q ^ (row & 7)) << 4);
                const size_t bo = (size_t)(n0 + row) * KTOT + bk + q * 8;
                cp16ca(base + 16384 + sw, Bh_ + bo);
                cp16ca(base + 24576 + sw, Bl_ + bo);
            }
            cp_commit();
        };

        float acc[2][4][4];
#pragma unroll
        for (int mt = 0; mt < 2; mt++)
#pragma unroll
            for (int nt = 0; nt < 4; nt++)
#pragma unroll
                for (int i = 0; i < 4; i++) acc[mt][nt][i] = 0.f;

        if (!preloaded) load_chunk(0, 0, xp, Bh, Bl);
        preloaded = false;
        load_chunk(1, 1, xp, Bh, Bl);

        for (int c = 0; c < NCH; c++) {
            const int s = c % 3;
            if (c >= NCH - 2) cp_wait0(); else cp_wait1();
            __syncthreads();
            if (c + 2 < NCH) load_chunk(c + 2, (c + 2) % 3, xp, Bh, Bl);

            const uint32_t ab  = sb + s * STG;
            const uint32_t bhb = ab + 16384;
            const uint32_t blb = ab + 24576;
#pragma unroll
            for (int ks = 0; ks < 4; ks++) {
                const int qk = (ks << 1) | lh;
                uint32_t a0[4], a1[4], bh0[4], bh1[4], bl0[4], bl1[4];
                ldsm4(a0,  ab  + rA0 * 128 + ((qk ^ (rA0 & 7)) << 4));
                ldsm4(a1,  ab  + rA1 * 128 + ((qk ^ (rA1 & 7)) << 4));
                ldsm4(bh0, bhb + rB0 * 128 + ((qk ^ (rB0 & 7)) << 4));
                ldsm4(bh1, bhb + rB1 * 128 + ((qk ^ (rB1 & 7)) << 4));
                ldsm4(bl0, blb + rB0 * 128 + ((qk ^ (rB0 & 7)) << 4));
                ldsm4(bl1, blb + rB1 * 128 + ((qk ^ (rB1 & 7)) << 4));
                // A * Bh
                mma16816(acc[0][0], a0, bh0[0], bh0[2]);
                mma16816(acc[0][1], a0, bh0[1], bh0[3]);
                mma16816(acc[0][2], a0, bh1[0], bh1[2]);
                mma16816(acc[0][3], a0, bh1[1], bh1[3]);
                mma16816(acc[1][0], a1, bh0[0], bh0[2]);
                mma16816(acc[1][1], a1, bh0[1], bh0[3]);
                mma16816(acc[1][2], a1, bh1[0], bh1[2]);
                mma16816(acc[1][3], a1, bh1[1], bh1[3]);
                // A * Bl
                mma16816(acc[0][0], a0, bl0[0], bl0[2]);
                mma16816(acc[0][1], a0, bl0[1], bl0[3]);
                mma16816(acc[0][2], a0, bl1[0], bl1[2]);
                mma16816(acc[0][3], a0, bl1[1], bl1[3]);
                mma16816(acc[1][0], a1, bl0[0], bl0[2]);
                mma16816(acc[1][1], a1, bl0[1], bl0[3]);
                mma16816(acc[1][2], a1, bl1[0], bl1[2]);
                mma16816(acc[1][3], a1, bl1[1], bl1[3]);
            }
        }

        // ---------------- fused LSTM epilogue ----------------
        {
            __half* __restrict__ ho = g_H[pp ^ 1];
#pragma unroll
            for (int mt = 0; mt < 2; mt++) {
#pragma unroll
                for (int nt = 0; nt < 4; nt++) {
                    float* d = acc[mt][nt];
                    float s0 = __shfl_xor_sync(0xFFFFFFFFu, d[0], 1);
                    float s1 = __shfl_xor_sync(0xFFFFFFFFu, d[1], 1);
                    float s2 = __shfl_xor_sync(0xFFFFFFFFu, d[2], 1);
                    float s3 = __shfl_xor_sync(0xFFFFFFFFu, d[3], 1);
                    float q0, q1, q2, q3; int r;
                    if (evenlane) { q0 = d[0]; q1 = d[1]; q2 = s0; q3 = s1; r = rbase; }
                    else          { q0 = s2; q1 = s3; q2 = d[2]; q3 = d[3]; r = rbase + 8; }
                    const int n = n0 + wn * 32 + nt * 8 + (c2 >> 1) * 4;  // gate base (j*4)
                    const int j = n >> 2;
                    const int b = m0 + wm * 32 + mt * 16 + r;
                    const float4 bb4 = *reinterpret_cast<const float4*>(br + n);
                    float iv = sigf(q0 + bb4.x);
                    float fv = sigf(q1 + bb4.y);
                    float gv = tanhf_(q2 + bb4.z);
                    float ov = sigf(q3 + bb4.w);
                    const int o = b * HH + j;
                    float cn = fv * g_c[o] + iv * gv;
                    g_c[o] = cn;
                    float hn = ov * tanhf_(cn);
                    g_hf[o] = hn;
                    ho[o] = __float2half_rn(hn);
                }
            }
        }

        // preload next step's x-chunk (independent of new h) to overlap the barrier
        if (step + 1 < NSTEP && step + 1 <= SS) {
            const __half* nx = (step + 1 < SS) ? (g_X + (size_t)(step + 1) * BB * FF)
                                               : (g_X + (size_t)(SS - 1) * BB * FF);
            const __half* nBh = (step + 1 >= SS) ? g_Bh_dec : g_Bh_enc;
            const __half* nBl = (step + 1 >= SS) ? g_Bl_dec : g_Bl_enc;
            load_chunk(0, 0, nx, nBh, nBl);
            preloaded = true;
        }

        epoch++;
        grid_barrier(128u * epoch);

        if (dec) {
            // ---------------- fc phase: pred = h @ Wfc^T + bfc ----------------
            const int tdec = step - SS;
            float* fcb = reinterpret_cast<float*>(smem + FC_OFF);
            const int b0 = cta * 2;
            for (int i = tid; i < 2 * (HH / 4); i += 256) {
                int rrow = i / (HH / 4), o = i % (HH / 4);
                float4 v = __ldcg(reinterpret_cast<const float4*>(
                    g_hf + (size_t)(b0 + rrow) * HH) + o);
                reinterpret_cast<float4*>(fcb)[i] = v;
            }
            __syncthreads();
            if (tid < 128) {
                int bl_ = tid >> 6, f = tid & 63;
                const float4* w4 = reinterpret_cast<const float4*>(Wfc + (size_t)f * HH);
                const float4* h4 = reinterpret_cast<const float4*>(fcb + bl_ * HH);
                float s = bfc[f];
#pragma unroll 4
                for (int k = 0; k < HH / 4; k++) {
                    float4 wv = w4[k], hv = h4[k];
                    s += wv.x * hv.x + wv.y * hv.y + wv.z * hv.z + wv.w * hv.w;
                }
                int b = b0 + bl_;
                g_Dx[b * FF + f] = __float2half_rn(s);
                out[(size_t)b * TT * FF + (size_t)tdec * FF + f] = s;
            }
            epoch++;
            grid_barrier(128u * epoch);
        }
    }
}

// ---------------- launch ----------------
extern "C" void kernel_launch(void* const* d_in, const int* in_sizes, int n_in,
                              void* d_out, int out_size)
{
    const float* x     = (const float*)d_in[0];
    const float* Wih_e = (const float*)d_in[1];
    const float* Whh_e = (const float*)d_in[2];
    const float* bih_e = (const float*)d_in[3];
    const float* bhh_e = (const float*)d_in[4];
    const float* Wih_d = (const float*)d_in[5];
    const float* Whh_d = (const float*)d_in[6];
    const float* bih_d = (const float*)d_in[7];
    const float* bhh_d = (const float*)d_in[8];
    const float* Wfc   = (const float*)d_in[9];
    const float* bfc   = (const float*)d_in[10];
    float* out = (float*)d_out;

    cudaFuncSetAttribute(lstm_persistent, cudaFuncAttributeMaxDynamicSharedMemorySize, SMEM_BYTES);

    prep_w<<<1024, 256>>>(Wih_e, Whh_e, bih_e, bhh_e, 0);
    prep_w<<<1024, 256>>>(Wih_d, Whh_d, bih_d, bhh_d, 1);
    prep_x<<<1024, 256>>>(x);
    zero_kernel<<<512, 256>>>();

    dim3 grid(GG / BN, BB / BM);   // (64, 2) = 128 CTAs, one wave
    lstm_persistent<<<grid, 256, SMEM_BYTES>>>(Wfc, bfc, out);
}

// round 9
// speedup vs baseline: 3.5388x; 1.2778x over previous
#include <cuda_runtime.h>
#include <cuda_fp16.h>
#include <cstdint>
#include <cstddef>

// Problem constants
#define BB 256      // batch
#define SS 512      // encoder sequence length
#define FF 64       // feature dim
#define HH 1024     // hidden dim
#define GG 4096     // 4*H gate rows
#define KTOT 1088   // F + H
#define TT 64       // prediction length
#define NSTEP (SS + TT)

// GEMM tiling: 17 chunks of K=64; each chunk holds A / Bh / Bl (2 split products)
#define KC 64
#define NCH 17
#define BM 128
#define BN 64
#define STG 32768                      // A 16K + Bh 8K + Bl 8K
#define FC_OFF (3 * STG)               // fc scratch (fp16 h rows) after the 3 stages
#define SMEM_BYTES (FC_OFF + 8192)

// ---------------- device globals ----------------
__device__ __align__(16) __half g_Bh_enc[GG * KTOT];  // weights hi fp16, rows j*4+g, K-major
__device__ __align__(16) __half g_Bl_enc[GG * KTOT];  // weights lo fp16
__device__ __align__(16) __half g_Bh_dec[GG * KTOT];
__device__ __align__(16) __half g_Bl_dec[GG * KTOT];
__device__ __align__(16) float g_br_enc[GG];          // combined bias, reordered
__device__ __align__(16) float g_br_dec[GG];
__device__ __align__(16) __half g_X[SS * BB * FF];    // encoder x, [t][b][f], fp16
__device__ __align__(16) __half g_H[2][BB * HH];      // hidden state fp16 (ping-pong)
__device__ __align__(16) __half g_Dx[BB * FF];        // decoder feedback x fp16
__device__ unsigned g_bar;                            // grid barrier counter

// ---------------- helpers ----------------
__device__ __forceinline__ uint32_t smem_u32(const void* p) {
    return (uint32_t)__cvta_generic_to_shared(p);
}
// L2-only (bypass L1): activations change across steps; L1 is NOT flushed inside
// a persistent kernel, so h/x loads must not be L1-cached.
__device__ __forceinline__ void cp16cg(uint32_t dst, const void* src) {
    asm volatile("cp.async.cg.shared.global [%0], [%1], 16;\n" :: "r"(dst), "l"(src));
}
// L1-cached: immutable weights
__device__ __forceinline__ void cp16ca(uint32_t dst, const void* src) {
    asm volatile("cp.async.ca.shared.global [%0], [%1], 16;\n" :: "r"(dst), "l"(src));
}
__device__ __forceinline__ void cp_commit() { asm volatile("cp.async.commit_group;\n"); }
__device__ __forceinline__ void cp_wait0()  { asm volatile("cp.async.wait_group 0;\n" ::: "memory"); }
__device__ __forceinline__ void cp_wait1()  { asm volatile("cp.async.wait_group 1;\n" ::: "memory"); }

__device__ __forceinline__ float sigf(float x)   { return 1.f / (1.f + __expf(-x)); }
__device__ __forceinline__ float tanhf_(float x) { return 2.f / (1.f + __expf(-2.f * x)) - 1.f; }

__device__ __forceinline__ void ldsm4(uint32_t* r, uint32_t addr) {
    asm volatile("ldmatrix.sync.aligned.m8n8.x4.shared.b16 {%0,%1,%2,%3}, [%4];"
        : "=r"(r[0]), "=r"(r[1]), "=r"(r[2]), "=r"(r[3]) : "r"(addr));
}
__device__ __forceinline__ void mma16816(float* d, const uint32_t* a, uint32_t b0, uint32_t b1) {
    asm volatile(
        "mma.sync.aligned.m16n8k16.row.col.f32.f16.f16.f32 "
        "{%0,%1,%2,%3}, {%4,%5,%6,%7}, {%8,%9}, {%0,%1,%2,%3};"
        : "+f"(d[0]), "+f"(d[1]), "+f"(d[2]), "+f"(d[3])
        : "r"(a[0]), "r"(a[1]), "r"(a[2]), "r"(a[3]), "r"(b0), "r"(b1));
}

// grid barrier: 128 CTAs, all resident (grid 128 <= 148 SMs, occ 1 -> single wave)
__device__ __forceinline__ void grid_barrier(unsigned target) {
    __threadfence();
    __syncthreads();
    if (threadIdx.x == 0) {
        atomicAdd(&g_bar, 1u);
        while (*(volatile unsigned*)&g_bar < target) __nanosleep(32);
    }
    __syncthreads();
    __threadfence();
}

// ---------------- prep kernels ----------------
__global__ void prep_w(const float* __restrict__ Wih, const float* __restrict__ Whh,
                       const float* __restrict__ bih, const float* __restrict__ bhh,
                       int dec)
{
    __half* Bh = dec ? g_Bh_dec : g_Bh_enc;
    __half* Bl = dec ? g_Bl_dec : g_Bl_enc;
    float* br = dec ? g_br_dec : g_br_enc;
    const int total = GG * KTOT;
    for (int idx = blockIdx.x * blockDim.x + threadIdx.x; idx < total;
         idx += gridDim.x * blockDim.x) {
        int r = idx / KTOT, k = idx - r * KTOT;
        int j = r >> 2, gg = r & 3;
        int srow = gg * HH + j;
        float w = (k < FF) ? Wih[srow * FF + k] : Whh[(size_t)srow * HH + (k - FF)];
        __half hi = __float2half_rn(w);
        __half lo = __float2half_rn(w - __half2float(hi));
        Bh[idx] = hi; Bl[idx] = lo;
    }
    for (int r = blockIdx.x * blockDim.x + threadIdx.x; r < GG;
         r += gridDim.x * blockDim.x) {
        int j = r >> 2, gg = r & 3;
        br[r] = bih[gg * HH + j] + bhh[gg * HH + j];
    }
}

__global__ void prep_x(const float* __restrict__ x)
{
    const int total = SS * BB * FF;
    for (int idx = blockIdx.x * blockDim.x + threadIdx.x; idx < total;
         idx += gridDim.x * blockDim.x) {
        int t = idx / (BB * FF);
        int rem = idx - t * (BB * FF);
        int b = rem / FF, f = rem - b * FF;
        g_X[idx] = __float2half_rn(x[(size_t)b * SS * FF + (size_t)t * FF + f]);
    }
}

__global__ void zero_kernel()
{
    if (blockIdx.x == 0 && threadIdx.x == 0) g_bar = 0;
    for (int i = blockIdx.x * blockDim.x + threadIdx.x; i < BB * HH;
         i += gridDim.x * blockDim.x) {
        g_H[0][i] = __float2half_rn(0.f);
    }
}

// ---------------- persistent fused LSTM (all 576 steps + decoder fc) ----------------
// grid (GG/BN=64, BB/BM=2) = 128 CTAs, 256 threads (8 warps, 4M x 2N), warp tile 32x32.
// D = A(fp16) @ (Bh + Bl)^T  (2 MMA products), fused LSTM epilogue.
// Cell state c lives in REGISTERS (8 per thread) for the whole run.
__global__ __launch_bounds__(256, 1)
void lstm_persistent(const float* __restrict__ Wfc, const float* __restrict__ bfc,
                     float* __restrict__ out)
{
    extern __shared__ __align__(128) char smem[];
    const uint32_t sb = smem_u32(smem);
    const int tid  = threadIdx.x;
    const int lane = tid & 31;
    const int wid  = tid >> 5;
    const int wm   = wid & 3;          // 0..3 (M)
    const int wn   = wid >> 2;         // 0..1 (N)
    const int n0   = blockIdx.x * BN;
    const int m0   = blockIdx.y * BM;
    const int cta  = blockIdx.y * 64 + blockIdx.x;

    const int lr = lane & 15, lh = lane >> 4;
    const int rA0 = wm * 32 + lr, rA1 = rA0 + 16;
    const int rB0 = wn * 32 + lr, rB1 = rB0 + 16;
    const int c2 = lane & 3;
    const bool evenlane = !(c2 & 1);
    const int rbase = lane >> 2;

    float creg[8];                     // persistent cell state, one per (mt,nt)
#pragma unroll
    for (int i = 0; i < 8; i++) creg[i] = 0.f;

    unsigned epoch = 0;
    bool preloaded = false;

    for (int step = 0; step < NSTEP; step++) {
        const bool dec = (step >= SS);
        const int pp = step & 1;
        const __half* __restrict__ Bh = dec ? g_Bh_dec : g_Bh_enc;
        const __half* __restrict__ Bl = dec ? g_Bl_dec : g_Bl_enc;
        const float* __restrict__ br = dec ? g_br_dec : g_br_enc;
        const __half* __restrict__ xp;
        if (step < SS)       xp = g_X + (size_t)step * BB * FF;
        else if (step == SS) xp = g_X + (size_t)(SS - 1) * BB * FF;
        else                 xp = g_Dx;
        const __half* __restrict__ hp = g_H[pp];

        // chunk c: A / Bh / Bl for K slice [c*64, c*64+64)
        auto load_chunk = [&](int c, int s, const __half* x_,
                              const __half* Bh_, const __half* Bl_) {
            const __half* ap; int astr, ak;
            if (c == 0) { ap = x_; astr = FF; ak = 0; }
            else        { ap = hp; astr = HH; ak = (c - 1) * KC; }
            const int bk = c * KC;
            const uint32_t base = sb + s * STG;
#pragma unroll
            for (int i = 0; i < 4; i++) {          // A: 128 rows x 8 segs of 16B
                int idx = tid + i * 256;
                int row = idx >> 3, q = idx & 7;
                uint32_t sw = (uint32_t)(row * 128) + ((q ^ (row & 7)) << 4);
                cp16cg(base + sw, ap + (size_t)(m0 + row) * astr + ak + q * 8);
            }
#pragma unroll
            for (int i = 0; i < 2; i++) {          // B: 64 rows x 8 segs (x2 buffers)
                int idx = tid + i * 256;
                int row = idx >> 3, q = idx & 7;
                uint32_t sw = (uint32_t)(row * 128) + ((q ^ (row & 7)) << 4);
                const size_t bo = (size_t)(n0 + row) * KTOT + bk + q * 8;
                cp16ca(base + 16384 + sw, Bh_ + bo);
                cp16ca(base + 24576 + sw, Bl_ + bo);
            }
            cp_commit();
        };

        float acc[2][4][4];
#pragma unroll
        for (int mt = 0; mt < 2; mt++)
#pragma unroll
            for (int nt = 0; nt < 4; nt++)
#pragma unroll
                for (int i = 0; i < 4; i++) acc[mt][nt][i] = 0.f;

        if (!preloaded) load_chunk(0, 0, xp, Bh, Bl);
        preloaded = false;
        load_chunk(1, 1, xp, Bh, Bl);

        for (int c = 0; c < NCH; c++) {
            const int s = c % 3;
            if (c >= NCH - 2) cp_wait0(); else cp_wait1();
            __syncthreads();
            if (c + 2 < NCH) load_chunk(c + 2, (c + 2) % 3, xp, Bh, Bl);

            const uint32_t ab  = sb + s * STG;
            const uint32_t bhb = ab + 16384;
            const uint32_t blb = ab + 24576;
#pragma unroll
            for (int ks = 0; ks < 4; ks++) {
                const int qk = (ks << 1) | lh;
                uint32_t a0[4], a1[4], bh0[4], bh1[4], bl0[4], bl1[4];
                ldsm4(a0,  ab  + rA0 * 128 + ((qk ^ (rA0 & 7)) << 4));
                ldsm4(a1,  ab  + rA1 * 128 + ((qk ^ (rA1 & 7)) << 4));
                ldsm4(bh0, bhb + rB0 * 128 + ((qk ^ (rB0 & 7)) << 4));
                ldsm4(bh1, bhb + rB1 * 128 + ((qk ^ (rB1 & 7)) << 4));
                ldsm4(bl0, blb + rB0 * 128 + ((qk ^ (rB0 & 7)) << 4));
                ldsm4(bl1, blb + rB1 * 128 + ((qk ^ (rB1 & 7)) << 4));
                // A * Bh
                mma16816(acc[0][0], a0, bh0[0], bh0[2]);
                mma16816(acc[0][1], a0, bh0[1], bh0[3]);
                mma16816(acc[0][2], a0, bh1[0], bh1[2]);
                mma16816(acc[0][3], a0, bh1[1], bh1[3]);
                mma16816(acc[1][0], a1, bh0[0], bh0[2]);
                mma16816(acc[1][1], a1, bh0[1], bh0[3]);
                mma16816(acc[1][2], a1, bh1[0], bh1[2]);
                mma16816(acc[1][3], a1, bh1[1], bh1[3]);
                // A * Bl
                mma16816(acc[0][0], a0, bl0[0], bl0[2]);
                mma16816(acc[0][1], a0, bl0[1], bl0[3]);
                mma16816(acc[0][2], a0, bl1[0], bl1[2]);
                mma16816(acc[0][3], a0, bl1[1], bl1[3]);
                mma16816(acc[1][0], a1, bl0[0], bl0[2]);
                mma16816(acc[1][1], a1, bl0[1], bl0[3]);
                mma16816(acc[1][2], a1, bl1[0], bl1[2]);
                mma16816(acc[1][3], a1, bl1[1], bl1[3]);
            }
        }

        // ---------------- fused LSTM epilogue (c in registers, h fp16 only) --------
        {
            __half* __restrict__ ho = g_H[pp ^ 1];
#pragma unroll
            for (int mt = 0; mt < 2; mt++) {
#pragma unroll
                for (int nt = 0; nt < 4; nt++) {
                    float* d = acc[mt][nt];
                    float s0 = __shfl_xor_sync(0xFFFFFFFFu, d[0], 1);
                    float s1 = __shfl_xor_sync(0xFFFFFFFFu, d[1], 1);
                    float s2 = __shfl_xor_sync(0xFFFFFFFFu, d[2], 1);
                    float s3 = __shfl_xor_sync(0xFFFFFFFFu, d[3], 1);
                    float q0, q1, q2, q3; int r;
                    if (evenlane) { q0 = d[0]; q1 = d[1]; q2 = s0; q3 = s1; r = rbase; }
                    else          { q0 = s2; q1 = s3; q2 = d[2]; q3 = d[3]; r = rbase + 8; }
                    const int n = n0 + wn * 32 + nt * 8 + (c2 >> 1) * 4;  // gate base (j*4)
                    const int j = n >> 2;
                    const int b = m0 + wm * 32 + mt * 16 + r;
                    const float4 bb4 = *reinterpret_cast<const float4*>(br + n);
                    float iv = sigf(q0 + bb4.x);
                    float fv = sigf(q1 + bb4.y);
                    float gv = tanhf_(q2 + bb4.z);
                    float ov = sigf(q3 + bb4.w);
                    float cn = fv * creg[mt * 4 + nt] + iv * gv;
                    creg[mt * 4 + nt] = cn;
                    float hn = ov * tanhf_(cn);
                    ho[b * HH + j] = __float2half_rn(hn);
                }
            }
        }

        // preload next step's x-chunk (independent of new h) to overlap the barrier
        if (step + 1 < NSTEP && step + 1 <= SS) {
            const __half* nx = (step + 1 < SS) ? (g_X + (size_t)(step + 1) * BB * FF)
                                               : (g_X + (size_t)(SS - 1) * BB * FF);
            const __half* nBh = (step + 1 >= SS) ? g_Bh_dec : g_Bh_enc;
            const __half* nBl = (step + 1 >= SS) ? g_Bl_dec : g_Bl_enc;
            load_chunk(0, 0, nx, nBh, nBl);
            preloaded = true;
        }

        epoch++;
        grid_barrier(128u * epoch);

        if (dec) {
            // ---------------- fc phase: pred = h @ Wfc^T + bfc (h from fp16) -------
            const int tdec = step - SS;
            __half* fcb = reinterpret_cast<__half*>(smem + FC_OFF);
            const int b0 = cta * 2;
            const __half* hsrc = g_H[pp ^ 1];
            // stage 2 rows x 1024 fp16 = 4KB = 256 x 16B, L2-only loads
            for (int i = tid; i < 256; i += 256) {
                int rrow = i >> 7, o = i & 127;
                uint4 v = __ldcg(reinterpret_cast<const uint4*>(
                    hsrc + (size_t)(b0 + rrow) * HH) + o);
                reinterpret_cast<uint4*>(fcb)[i] = v;
            }
            __syncthreads();
            if (tid < 128) {
                int bl_ = tid >> 6, f = tid & 63;
                const float4* w4 = reinterpret_cast<const float4*>(Wfc + (size_t)f * HH);
                const __half2* h2 = reinterpret_cast<const __half2*>(fcb + bl_ * HH);
                float s = bfc[f];
#pragma unroll 4
                for (int k = 0; k < HH / 4; k++) {
                    float4 wv = w4[k];
                    float2 fa = __half22float2(h2[2 * k]);
                    float2 fb = __half22float2(h2[2 * k + 1]);
                    s += wv.x * fa.x + wv.y * fa.y + wv.z * fb.x + wv.w * fb.y;
                }
                int b = b0 + bl_;
                g_Dx[b * FF + f] = __float2half_rn(s);
                out[(size_t)b * TT * FF + (size_t)tdec * FF + f] = s;
            }
            epoch++;
            grid_barrier(128u * epoch);
        }
    }
}

// ---------------- launch ----------------
extern "C" void kernel_launch(void* const* d_in, const int* in_sizes, int n_in,
                              void* d_out, int out_size)
{
    const float* x     = (const float*)d_in[0];
    const float* Wih_e = (const float*)d_in[1];
    const float* Whh_e = (const float*)d_in[2];
    const float* bih_e = (const float*)d_in[3];
    const float* bhh_e = (const float*)d_in[4];
    const float* Wih_d = (const float*)d_in[5];
    const float* Whh_d = (const float*)d_in[6];
    const float* bih_d = (const float*)d_in[7];
    const float* bhh_d = (const float*)d_in[8];
    const float* Wfc   = (const float*)d_in[9];
    const float* bfc   = (const float*)d_in[10];
    float* out = (float*)d_out;

    cudaFuncSetAttribute(lstm_persistent, cudaFuncAttributeMaxDynamicSharedMemorySize, SMEM_BYTES);

    prep_w<<<1024, 256>>>(Wih_e, Whh_e, bih_e, bhh_e, 0);
    prep_w<<<1024, 256>>>(Wih_d, Whh_d, bih_d, bhh_d, 1);
    prep_x<<<1024, 256>>>(x);
    zero_kernel<<<512, 256>>>();

    dim3 grid(GG / BN, BB / BM);   // (64, 2) = 128 CTAs, one wave
    lstm_persistent<<<grid, 256, SMEM_BYTES>>>(Wfc, bfc, out);
}

// round 10
// speedup vs baseline: 4.6776x; 1.3218x over previous
#include <cuda_runtime.h>
#include <cuda_fp16.h>
#include <cstdint>
#include <cstddef>

// Problem constants
#define BB 256      // batch
#define SS 512      // encoder sequence length
#define FF 64       // feature dim
#define HH 1024     // hidden dim
#define GG 4096     // 4*H gate rows
#define KTOT 1088   // F + H
#define TT 64       // prediction length
#define NSTEP (SS + TT)

// GEMM tiling: 17 chunks of K=64; single fp16 product (A * B)
#define KC 64
#define NCH 17
#define BM 128
#define BN 64
#define STG 24576                      // A 16K + B 8K
#define FC_OFF (3 * STG)               // fc scratch (fp16 h rows) after the 3 stages
#define SMEM_BYTES (FC_OFF + 8192)

// ---------------- device globals ----------------
__device__ __align__(16) __half g_B_enc[GG * KTOT];   // weights fp16, rows j*4+g, K-major
__device__ __align__(16) __half g_B_dec[GG * KTOT];
__device__ __align__(16) float g_br_enc[GG];          // combined bias, reordered
__device__ __align__(16) float g_br_dec[GG];
__device__ __align__(16) __half g_X[SS * BB * FF];    // encoder x, [t][b][f], fp16
__device__ __align__(16) __half g_H[2][BB * HH];      // hidden state fp16 (ping-pong)
__device__ __align__(16) __half g_Dx[BB * FF];        // decoder feedback x fp16
__device__ unsigned g_bar;                            // grid barrier counter

// ---------------- helpers ----------------
__device__ __forceinline__ uint32_t smem_u32(const void* p) {
    return (uint32_t)__cvta_generic_to_shared(p);
}
// L2-only (bypass L1): activations change across steps; L1 is NOT flushed inside
// a persistent kernel, so h/x loads must not be L1-cached.
__device__ __forceinline__ void cp16cg(uint32_t dst, const void* src) {
    asm volatile("cp.async.cg.shared.global [%0], [%1], 16;\n" :: "r"(dst), "l"(src));
}
// L1-cached: immutable weights
__device__ __forceinline__ void cp16ca(uint32_t dst, const void* src) {
    asm volatile("cp.async.ca.shared.global [%0], [%1], 16;\n" :: "r"(dst), "l"(src));
}
__device__ __forceinline__ void cp_commit() { asm volatile("cp.async.commit_group;\n"); }
__device__ __forceinline__ void cp_wait0()  { asm volatile("cp.async.wait_group 0;\n" ::: "memory"); }
__device__ __forceinline__ void cp_wait1()  { asm volatile("cp.async.wait_group 1;\n" ::: "memory"); }

__device__ __forceinline__ float sigf(float x)   { return 1.f / (1.f + __expf(-x)); }
__device__ __forceinline__ float tanhf_(float x) { return 2.f / (1.f + __expf(-2.f * x)) - 1.f; }

__device__ __forceinline__ void ldsm4(uint32_t* r, uint32_t addr) {
    asm volatile("ldmatrix.sync.aligned.m8n8.x4.shared.b16 {%0,%1,%2,%3}, [%4];"
        : "=r"(r[0]), "=r"(r[1]), "=r"(r[2]), "=r"(r[3]) : "r"(addr));
}
__device__ __forceinline__ void mma16816(float* d, const uint32_t* a, uint32_t b0, uint32_t b1) {
    asm volatile(
        "mma.sync.aligned.m16n8k16.row.col.f32.f16.f16.f32 "
        "{%0,%1,%2,%3}, {%4,%5,%6,%7}, {%8,%9}, {%0,%1,%2,%3};"
        : "+f"(d[0]), "+f"(d[1]), "+f"(d[2]), "+f"(d[3])
        : "r"(a[0]), "r"(a[1]), "r"(a[2]), "r"(a[3]), "r"(b0), "r"(b1));
}

// grid barrier: 128 CTAs, all resident (grid 128 <= 148 SMs, occ 1 -> single wave)
__device__ __forceinline__ void grid_barrier(unsigned target) {
    __threadfence();
    __syncthreads();
    if (threadIdx.x == 0) {
        atomicAdd(&g_bar, 1u);
        while (*(volatile unsigned*)&g_bar < target) __nanosleep(32);
    }
    __syncthreads();
    __threadfence();
}

// ---------------- prep kernels ----------------
__global__ void prep_w(const float* __restrict__ Wih, const float* __restrict__ Whh,
                       const float* __restrict__ bih, const float* __restrict__ bhh,
                       int dec)
{
    __half* B = dec ? g_B_dec : g_B_enc;
    float* br = dec ? g_br_dec : g_br_enc;
    const int total = GG * KTOT;
    for (int idx = blockIdx.x * blockDim.x + threadIdx.x; idx < total;
         idx += gridDim.x * blockDim.x) {
        int r = idx / KTOT, k = idx - r * KTOT;
        int j = r >> 2, gg = r & 3;
        int srow = gg * HH + j;
        float w = (k < FF) ? Wih[srow * FF + k] : Whh[(size_t)srow * HH + (k - FF)];
        B[idx] = __float2half_rn(w);
    }
    for (int r = blockIdx.x * blockDim.x + threadIdx.x; r < GG;
         r += gridDim.x * blockDim.x) {
        int j = r >> 2, gg = r & 3;
        br[r] = bih[gg * HH + j] + bhh[gg * HH + j];
    }
}

__global__ void prep_x(const float* __restrict__ x)
{
    const int total = SS * BB * FF;
    for (int idx = blockIdx.x * blockDim.x + threadIdx.x; idx < total;
         idx += gridDim.x * blockDim.x) {
        int t = idx / (BB * FF);
        int rem = idx - t * (BB * FF);
        int b = rem / FF, f = rem - b * FF;
        g_X[idx] = __float2half_rn(x[(size_t)b * SS * FF + (size_t)t * FF + f]);
    }
}

__global__ void zero_kernel()
{
    if (blockIdx.x == 0 && threadIdx.x == 0) g_bar = 0;
    for (int i = blockIdx.x * blockDim.x + threadIdx.x; i < BB * HH;
         i += gridDim.x * blockDim.x) {
        g_H[0][i] = __float2half_rn(0.f);
    }
}

// ---------------- persistent fused LSTM (all 576 steps + decoder fc) ----------------
// grid (GG/BN=64, BB/BM=2) = 128 CTAs, 256 threads (8 warps, 4M x 2N), warp tile 32x32.
// D = A(fp16) @ B(fp16)^T  (single product), fused LSTM epilogue.
// Cell state c lives in REGISTERS (8 per thread) for the whole run.
__global__ __launch_bounds__(256, 1)
void lstm_persistent(const float* __restrict__ Wfc, const float* __restrict__ bfc,
                     float* __restrict__ out)
{
    extern __shared__ __align__(128) char smem[];
    const uint32_t sb = smem_u32(smem);
    const int tid  = threadIdx.x;
    const int lane = tid & 31;
    const int wid  = tid >> 5;
    const int wm   = wid & 3;          // 0..3 (M)
    const int wn   = wid >> 2;         // 0..1 (N)
    const int n0   = blockIdx.x * BN;
    const int m0   = blockIdx.y * BM;
    const int cta  = blockIdx.y * 64 + blockIdx.x;

    const int lr = lane & 15, lh = lane >> 4;
    const int rA0 = wm * 32 + lr, rA1 = rA0 + 16;
    const int rB0 = wn * 32 + lr, rB1 = rB0 + 16;
    const int c2 = lane & 3;
    const bool evenlane = !(c2 & 1);
    const int rbase = lane >> 2;

    float creg[8];                     // persistent cell state, one per (mt,nt)
#pragma unroll
    for (int i = 0; i < 8; i++) creg[i] = 0.f;

    unsigned epoch = 0;
    bool preloaded = false;

    for (int step = 0; step < NSTEP; step++) {
        const bool dec = (step >= SS);
        const int pp = step & 1;
        const __half* __restrict__ B = dec ? g_B_dec : g_B_enc;
        const float* __restrict__ br = dec ? g_br_dec : g_br_enc;
        const __half* __restrict__ xp;
        if (step < SS)       xp = g_X + (size_t)step * BB * FF;
        else if (step == SS) xp = g_X + (size_t)(SS - 1) * BB * FF;
        else                 xp = g_Dx;
        const __half* __restrict__ hp = g_H[pp];

        // chunk c: A / B for K slice [c*64, c*64+64)
        auto load_chunk = [&](int c, int s, const __half* x_, const __half* B_) {
            const __half* ap; int astr, ak;
            if (c == 0) { ap = x_; astr = FF; ak = 0; }
            else        { ap = hp; astr = HH; ak = (c - 1) * KC; }
            const int bk = c * KC;
            const uint32_t base = sb + s * STG;
#pragma unroll
            for (int i = 0; i < 4; i++) {          // A: 128 rows x 8 segs of 16B
                int idx = tid + i * 256;
                int row = idx >> 3, q = idx & 7;
                uint32_t sw = (uint32_t)(row * 128) + ((q ^ (row & 7)) << 4);
                cp16cg(base + sw, ap + (size_t)(m0 + row) * astr + ak + q * 8);
            }
#pragma unroll
            for (int i = 0; i < 2; i++) {          // B: 64 rows x 8 segs
                int idx = tid + i * 256;
                int row = idx >> 3, q = idx & 7;
                uint32_t sw = (uint32_t)(row * 128) + ((q ^ (row & 7)) << 4);
                cp16ca(base + 16384 + sw, B_ + (size_t)(n0 + row) * KTOT + bk + q * 8);
            }
            cp_commit();
        };

        float acc[2][4][4];
#pragma unroll
        for (int mt = 0; mt < 2; mt++)
#pragma unroll
            for (int nt = 0; nt < 4; nt++)
#pragma unroll
                for (int i = 0; i < 4; i++) acc[mt][nt][i] = 0.f;

        if (!preloaded) load_chunk(0, 0, xp, B);
        preloaded = false;
        load_chunk(1, 1, xp, B);

        for (int c = 0; c < NCH; c++) {
            const int s = c % 3;
            if (c >= NCH - 2) cp_wait0(); else cp_wait1();
            __syncthreads();
            if (c + 2 < NCH) load_chunk(c + 2, (c + 2) % 3, xp, B);

            const uint32_t ab = sb + s * STG;
            const uint32_t bb = ab + 16384;
#pragma unroll
            for (int ks = 0; ks < 4; ks++) {
                const int qk = (ks << 1) | lh;
                uint32_t a0[4], a1[4], b0[4], b1[4];
                ldsm4(a0, ab + rA0 * 128 + ((qk ^ (rA0 & 7)) << 4));
                ldsm4(a1, ab + rA1 * 128 + ((qk ^ (rA1 & 7)) << 4));
                ldsm4(b0, bb + rB0 * 128 + ((qk ^ (rB0 & 7)) << 4));
                ldsm4(b1, bb + rB1 * 128 + ((qk ^ (rB1 & 7)) << 4));
                mma16816(acc[0][0], a0, b0[0], b0[2]);
                mma16816(acc[0][1], a0, b0[1], b0[3]);
                mma16816(acc[0][2], a0, b1[0], b1[2]);
                mma16816(acc[0][3], a0, b1[1], b1[3]);
                mma16816(acc[1][0], a1, b0[0], b0[2]);
                mma16816(acc[1][1], a1, b0[1], b0[3]);
                mma16816(acc[1][2], a1, b1[0], b1[2]);
                mma16816(acc[1][3], a1, b1[1], b1[3]);
            }
        }

        // ---------------- fused LSTM epilogue (c in registers, h fp16 only) --------
        {
            __half* __restrict__ ho = g_H[pp ^ 1];
#pragma unroll
            for (int mt = 0; mt < 2; mt++) {
#pragma unroll
                for (int nt = 0; nt < 4; nt++) {
                    float* d = acc[mt][nt];
                    float s0 = __shfl_xor_sync(0xFFFFFFFFu, d[0], 1);
                    float s1 = __shfl_xor_sync(0xFFFFFFFFu, d[1], 1);
                    float s2 = __shfl_xor_sync(0xFFFFFFFFu, d[2], 1);
                    float s3 = __shfl_xor_sync(0xFFFFFFFFu, d[3], 1);
                    float q0, q1, q2, q3; int r;
                    if (evenlane) { q0 = d[0]; q1 = d[1]; q2 = s0; q3 = s1; r = rbase; }
                    else          { q0 = s2; q1 = s3; q2 = d[2]; q3 = d[3]; r = rbase + 8; }
                    const int n = n0 + wn * 32 + nt * 8 + (c2 >> 1) * 4;  // gate base (j*4)
                    const int j = n >> 2;
                    const int b = m0 + wm * 32 + mt * 16 + r;
                    const float4 bb4 = *reinterpret_cast<const float4*>(br + n);
                    float iv = sigf(q0 + bb4.x);
                    float fv = sigf(q1 + bb4.y);
                    float gv = tanhf_(q2 + bb4.z);
                    float ov = sigf(q3 + bb4.w);
                    float cn = fv * creg[mt * 4 + nt] + iv * gv;
                    creg[mt * 4 + nt] = cn;
                    float hn = ov * tanhf_(cn);
                    ho[b * HH + j] = __float2half_rn(hn);
                }
            }
        }

        // preload next step's x-chunk (independent of new h) to overlap the barrier
        if (step + 1 < NSTEP && step + 1 <= SS) {
            const __half* nx = (step + 1 < SS) ? (g_X + (size_t)(step + 1) * BB * FF)
                                               : (g_X + (size_t)(SS - 1) * BB * FF);
            const __half* nB = (step + 1 >= SS) ? g_B_dec : g_B_enc;
            load_chunk(0, 0, nx, nB);
            preloaded = true;
        }

        epoch++;
        grid_barrier(128u * epoch);

        if (dec) {
            // ---------------- fc phase: pred = h @ Wfc^T + bfc (h from fp16) -------
            const int tdec = step - SS;
            __half* fcb = reinterpret_cast<__half*>(smem + FC_OFF);
            const int b0 = cta * 2;
            const __half* hsrc = g_H[pp ^ 1];
            // stage 2 rows x 1024 fp16 = 4KB = 256 x 16B, L2-only loads
            for (int i = tid; i < 256; i += 256) {
                int rrow = i >> 7, o = i & 127;
                uint4 v = __ldcg(reinterpret_cast<const uint4*>(
                    hsrc + (size_t)(b0 + rrow) * HH) + o);
                reinterpret_cast<uint4*>(fcb)[i] = v;
            }
            __syncthreads();
            if (tid < 128) {
                int bl_ = tid >> 6, f = tid & 63;
                const float4* w4 = reinterpret_cast<const float4*>(Wfc + (size_t)f * HH);
                const __half2* h2 = reinterpret_cast<const __half2*>(fcb + bl_ * HH);
                float s = bfc[f];
#pragma unroll 4
                for (int k = 0; k < HH / 4; k++) {
                    float4 wv = w4[k];
                    float2 fa = __half22float2(h2[2 * k]);
                    float2 fb = __half22float2(h2[2 * k + 1]);
                    s += wv.x * fa.x + wv.y * fa.y + wv.z * fb.x + wv.w * fb.y;
                }
                int b = b0 + bl_;
                g_Dx[b * FF + f] = __float2half_rn(s);
                out[(size_t)b * TT * FF + (size_t)tdec * FF + f] = s;
            }
            epoch++;
            grid_barrier(128u * epoch);
        }
    }
}

// ---------------- launch ----------------
extern "C" void kernel_launch(void* const* d_in, const int* in_sizes, int n_in,
                              void* d_out, int out_size)
{
    const float* x     = (const float*)d_in[0];
    const float* Wih_e = (const float*)d_in[1];
    const float* Whh_e = (const float*)d_in[2];
    const float* bih_e = (const float*)d_in[3];
    const float* bhh_e = (const float*)d_in[4];
    const float* Wih_d = (const float*)d_in[5];
    const float* Whh_d = (const float*)d_in[6];
    const float* bih_d = (const float*)d_in[7];
    const float* bhh_d = (const float*)d_in[8];
    const float* Wfc   = (const float*)d_in[9];
    const float* bfc   = (const float*)d_in[10];
    float* out = (float*)d_out;

    cudaFuncSetAttribute(lstm_persistent, cudaFuncAttributeMaxDynamicSharedMemorySize, SMEM_BYTES);

    prep_w<<<1024, 256>>>(Wih_e, Whh_e, bih_e, bhh_e, 0);
    prep_w<<<1024, 256>>>(Wih_d, Whh_d, bih_d, bhh_d, 1);
    prep_x<<<1024, 256>>>(x);
    zero_kernel<<<512, 256>>>();

    dim3 grid(GG / BN, BB / BM);   // (64, 2) = 128 CTAs, one wave
    lstm_persistent<<<grid, 256, SMEM_BYTES>>>(Wfc, bfc, out);
}

// round 12
// speedup vs baseline: 4.8270x; 1.0319x over previous
#include <cuda_runtime.h>
#include <cuda_fp16.h>
#include <cstdint>
#include <cstddef>

// Problem constants
#define BB 256      // batch
#define SS 512      // encoder sequence length
#define FF 64       // feature dim
#define HH 1024     // hidden dim
#define GG 4096     // 4*H gate rows
#define KTOT 1088   // F + H
#define TT 64       // prediction length
#define NSTEP (SS + TT)

// GEMM tiling: 128-wide commit chunks (2 x 64-wide swizzled sub-tiles), 2 stages
#define BM 128
#define BN 64
#define STG 49152                      // A 2x16K + B 2x8K
#define FC_OFF (2 * STG)               // fc scratch after the 2 stages
#define SMEM_BYTES (FC_OFF + 8192)

// ---------------- device globals ----------------
__device__ __align__(16) __half g_B_enc[GG * KTOT];   // enc weights fp16, rows j*4+g, K-major
__device__ __align__(16) __half g_B_dec[GG * KTOT];   // dec weights (step SS only, has x part)
__device__ __align__(16) __half g_B_de[GG * HH];      // dec folded weights: Whh + Wih@Wfc
__device__ __align__(16) float g_br_enc[GG];          // combined bias, reordered
__device__ __align__(16) float g_br_dec[GG];
__device__ __align__(16) float g_br_de[GG];           // folded bias: b_dec + Wih@bfc
__device__ __align__(16) __half g_X[SS * BB * FF];    // encoder x, [t][b][f], fp16
__device__ __align__(16) __half g_H[2][BB * HH];      // hidden state fp16 (ping-pong)
__device__ unsigned g_bar;                            // grid barrier counter

// ---------------- helpers ----------------
__device__ __forceinline__ uint32_t smem_u32(const void* p) {
    return (uint32_t)__cvta_generic_to_shared(p);
}
// L2-only: activations change across steps (persistent kernel -> no L1 flush)
__device__ __forceinline__ void cp16cg(uint32_t dst, const void* src) {
    asm volatile("cp.async.cg.shared.global [%0], [%1], 16;\n" :: "r"(dst), "l"(src));
}
// L1-cached: immutable weights
__device__ __forceinline__ void cp16ca(uint32_t dst, const void* src) {
    asm volatile("cp.async.ca.shared.global [%0], [%1], 16;\n" :: "r"(dst), "l"(src));
}
__device__ __forceinline__ void cp_commit() { asm volatile("cp.async.commit_group;\n"); }
__device__ __forceinline__ void cp_wait0()  { asm volatile("cp.async.wait_group 0;\n" ::: "memory"); }

__device__ __forceinline__ float sigf(float x)   { return 1.f / (1.f + __expf(-x)); }
__device__ __forceinline__ float tanhf_(float x) { return 2.f / (1.f + __expf(-2.f * x)) - 1.f; }

__device__ __forceinline__ void ldsm4(uint32_t* r, uint32_t addr) {
    asm volatile("ldmatrix.sync.aligned.m8n8.x4.shared.b16 {%0,%1,%2,%3}, [%4];"
        : "=r"(r[0]), "=r"(r[1]), "=r"(r[2]), "=r"(r[3]) : "r"(addr));
}
__device__ __forceinline__ void mma16816(float* d, const uint32_t* a, uint32_t b0, uint32_t b1) {
    asm volatile(
        "mma.sync.aligned.m16n8k16.row.col.f32.f16.f16.f32 "
        "{%0,%1,%2,%3}, {%4,%5,%6,%7}, {%8,%9}, {%0,%1,%2,%3};"
        : "+f"(d[0]), "+f"(d[1]), "+f"(d[2]), "+f"(d[3])
        : "r"(a[0]), "r"(a[1]), "r"(a[2]), "r"(a[3]), "r"(b0), "r"(b1));
}

// grid barrier: 128 CTAs, all resident (single wave)
__device__ __forceinline__ void grid_barrier(unsigned target) {
    __threadfence();
    __syncthreads();
    if (threadIdx.x == 0) {
        atomicAdd(&g_bar, 1u);
        while (*(volatile unsigned*)&g_bar < target) __nanosleep(32);
    }
    __syncthreads();
    __threadfence();
}

// ---------------- prep kernels ----------------
__global__ void prep_w(const float* __restrict__ Wih, const float* __restrict__ Whh,
                       const float* __restrict__ bih, const float* __restrict__ bhh,
                       int dec)
{
    __half* B = dec ? g_B_dec : g_B_enc;
    float* br = dec ? g_br_dec : g_br_enc;
    const int total = GG * KTOT;
    for (int idx = blockIdx.x * blockDim.x + threadIdx.x; idx < total;
         idx += gridDim.x * blockDim.x) {
        int r = idx / KTOT, k = idx - r * KTOT;
        int j = r >> 2, gg = r & 3;
        int srow = gg * HH + j;
        float w = (k < FF) ? Wih[srow * FF + k] : Whh[(size_t)srow * HH + (k - FF)];
        B[idx] = __float2half_rn(w);
    }
    for (int r = blockIdx.x * blockDim.x + threadIdx.x; r < GG;
         r += gridDim.x * blockDim.x) {
        int j = r >> 2, gg = r & 3;
        br[r] = bih[gg * HH + j] + bhh[gg * HH + j];
    }
}

// folded decoder weights: W_eff = W_hh_dec + W_ih_dec @ Wfc ; b_eff = b_dec + W_ih_dec @ bfc
// grid (16 k-tiles, 16 row-groups), 256 threads
__global__ void prep_wcomb(const float* __restrict__ Wih_d, const float* __restrict__ Whh_d,
                           const float* __restrict__ bih_d, const float* __restrict__ bhh_d,
                           const float* __restrict__ Wfc, const float* __restrict__ bfc)
{
    __shared__ float wt[64][65];       // Wfc[f][k0+kk]
    const int k0 = blockIdx.x * 64;
    const int r0 = blockIdx.y * 256;
    const int tid = threadIdx.x;
    for (int i = tid; i < 64 * 64; i += 256) {
        int f = i >> 6, kk = i & 63;
        wt[f][kk] = Wfc[f * HH + k0 + kk];
    }
    __syncthreads();
    const int kk = tid & 63;
    const int rr = tid >> 6;           // 0..3
    for (int r = r0 + rr; r < r0 + 256; r += 4) {
        int j = r >> 2, gg = r & 3, srow = gg * HH + j;
        const float* wi = Wih_d + srow * FF;
        float s = Whh_d[(size_t)srow * HH + k0 + kk];
#pragma unroll 16
        for (int f = 0; f < 64; f++) s += wi[f] * wt[f][kk];
        g_B_de[(size_t)r * HH + k0 + kk] = __float2half_rn(s);
    }
    if (blockIdx.x == 0) {
        for (int r = r0 + tid; r < r0 + 256; r += 256) {
            int j = r >> 2, gg = r & 3, srow = gg * HH + j;
            float s = bih_d[srow] + bhh_d[srow];
            const float* wi = Wih_d + srow * FF;
#pragma unroll 16
            for (int f = 0; f < 64; f++) s += wi[f] * bfc[f];
            g_br_de[r] = s;
        }
    }
}

__global__ void prep_x(const float* __restrict__ x)
{
    const int total = SS * BB * FF;
    for (int idx = blockIdx.x * blockDim.x + threadIdx.x; idx < total;
         idx += gridDim.x * blockDim.x) {
        int t = idx / (BB * FF);
        int rem = idx - t * (BB * FF);
        int b = rem / FF, f = rem - b * FF;
        g_X[idx] = __float2half_rn(x[(size_t)b * SS * FF + (size_t)t * FF + f]);
    }
}

__global__ void zero_kernel()
{
    if (blockIdx.x == 0 && threadIdx.x == 0) g_bar = 0;
    for (int i = blockIdx.x * blockDim.x + threadIdx.x; i < BB * HH;
         i += gridDim.x * blockDim.x) {
        g_H[0][i] = __float2half_rn(0.f);
    }
}

// ---------------- persistent fused LSTM ----------------
// grid (GG/BN=64, BB/BM=2) = 128 CTAs, 256 threads (8 warps, 4M x 2N), warp tile 32x32.
// Encoder + step SS: K=1088 ([x|h]); decoder steps > SS: K=1024 (h only, folded W).
// Cell state c in registers. One grid barrier per step. fc (pred) after barrier.
__global__ __launch_bounds__(256, 1)
void lstm_persistent(const float* __restrict__ Wfc, const float* __restrict__ bfc,
                     float* __restrict__ out)
{
    extern __shared__ __align__(128) char smem[];
    const uint32_t sb = smem_u32(smem);
    const int tid  = threadIdx.x;
    const int lane = tid & 31;
    const int wid  = tid >> 5;
    const int wm   = wid & 3;          // 0..3 (M)
    const int wn   = wid >> 2;         // 0..1 (N)
    const int n0   = blockIdx.x * BN;
    const int m0   = blockIdx.y * BM;
    const int cta  = blockIdx.y * 64 + blockIdx.x;

    const int lr = lane & 15, lh = lane >> 4;
    const int rA0 = wm * 32 + lr, rA1 = rA0 + 16;
    const int rB0 = wn * 32 + lr, rB1 = rB0 + 16;
    const int c2 = lane & 3;
    const bool evenlane = !(c2 & 1);
    const int rbase = lane >> 2;

    float creg[8];                     // persistent cell state, one per (mt,nt)
#pragma unroll
    for (int i = 0; i < 8; i++) creg[i] = 0.f;

    bool preloaded = false;

    for (int step = 0; step < NSTEP; step++) {
        const bool de = (step > SS);           // folded decoder steps
        const bool dec = (step >= SS);
        const int pp = step & 1;
        const int nch = de ? 8 : 9;
        const __half* __restrict__ Bp = de ? g_B_de : (dec ? g_B_dec : g_B_enc);
        const int bstr = de ? HH : KTOT;
        const float* __restrict__ br = de ? g_br_de : (dec ? g_br_dec : g_br_enc);
        const __half* __restrict__ xp = (step < SS)
            ? g_X + (size_t)step * BB * FF
            : g_X + (size_t)(SS - 1) * BB * FF;   // step == SS; unused for de
        const __half* __restrict__ hp = g_H[pp];

        // one 64-wide sub-tile: A (128 rows) + B (64 rows)
        auto load_sub = [&](uint32_t aBase, uint32_t bBase,
                            const __half* ap, int astr, int ak,
                            const __half* bp, int bs, int bk) {
#pragma unroll
            for (int i = 0; i < 4; i++) {
                int idx = tid + i * 256;
                int row = idx >> 3, q = idx & 7;
                uint32_t sw = (uint32_t)(row * 128) + ((q ^ (row & 7)) << 4);
                cp16cg(aBase + sw, ap + (size_t)(m0 + row) * astr + ak + q * 8);
            }
#pragma unroll
            for (int i = 0; i < 2; i++) {
                int idx = tid + i * 256;
                int row = idx >> 3, q = idx & 7;
                uint32_t sw = (uint32_t)(row * 128) + ((q ^ (row & 7)) << 4);
                cp16ca(bBase + sw, bp + (size_t)(n0 + row) * bs + bk + q * 8);
            }
        };

        // chunk c into stage s (1 commit). enc chunk0 = x (1 sub); others = 2 subs.
        // NOTE: for non-folded steps, B column index is GLOBAL K (k0), but the A
        // operand for k >= 64 is h at offset k0 - 64 (the 64-wide x prefix).
        auto load_chunk = [&](int c, int s, const __half* x_, const __half* B_,
                              int bs, bool de_) {
            const uint32_t base = sb + s * STG;
            if (de_) {
                int k0 = c * 128;
                load_sub(base,         base + 32768, hp, HH, k0,      B_, bs, k0);
                load_sub(base + 16384, base + 40960, hp, HH, k0 + 64, B_, bs, k0 + 64);
            } else if (c == 0) {
                load_sub(base, base + 32768, x_, FF, 0, B_, bs, 0);
            } else {
                int k0 = 64 + (c - 1) * 128;
                load_sub(base,         base + 32768, hp, HH, k0 - 64, B_, bs, k0);
                load_sub(base + 16384, base + 40960, hp, HH, k0,      B_, bs, k0 + 64);
            }
            cp_commit();
        };

        float acc[2][4][4];
#pragma unroll
        for (int mt = 0; mt < 2; mt++)
#pragma unroll
            for (int nt = 0; nt < 4; nt++)
#pragma unroll
                for (int i = 0; i < 4; i++) acc[mt][nt][i] = 0.f;

        if (!preloaded) load_chunk(0, 0, xp, Bp, bstr, de);
        preloaded = false;

        for (int c = 0; c < nch; c++) {
            const int s = c & 1;
            cp_wait0();
            __syncthreads();
            if (c + 1 < nch) load_chunk(c + 1, s ^ 1, xp, Bp, bstr, de);

            const int nsub = (!de && c == 0) ? 1 : 2;
            for (int sub = 0; sub < nsub; sub++) {
                const uint32_t ab = sb + s * STG + sub * 16384;
                const uint32_t bb = sb + s * STG + 32768 + sub * 8192;
#pragma unroll
                for (int ks = 0; ks < 4; ks++) {
                    const int qk = (ks << 1) | lh;
                    uint32_t a0[4], a1[4], b0[4], b1[4];
                    ldsm4(a0, ab + rA0 * 128 + ((qk ^ (rA0 & 7)) << 4));
                    ldsm4(a1, ab + rA1 * 128 + ((qk ^ (rA1 & 7)) << 4));
                    ldsm4(b0, bb + rB0 * 128 + ((qk ^ (rB0 & 7)) << 4));
                    ldsm4(b1, bb + rB1 * 128 + ((qk ^ (rB1 & 7)) << 4));
                    mma16816(acc[0][0], a0, b0[0], b0[2]);
                    mma16816(acc[0][1], a0, b0[1], b0[3]);
                    mma16816(acc[0][2], a0, b1[0], b1[2]);
                    mma16816(acc[0][3], a0, b1[1], b1[3]);
                    mma16816(acc[1][0], a1, b0[0], b0[2]);
                    mma16816(acc[1][1], a1, b0[1], b0[3]);
                    mma16816(acc[1][2], a1, b1[0], b1[2]);
                    mma16816(acc[1][3], a1, b1[1], b1[3]);
                }
            }
        }

        // ---------------- fused LSTM epilogue (c in registers, h fp16) ----------
        {
            __half* __restrict__ ho = g_H[pp ^ 1];
#pragma unroll
            for (int mt = 0; mt < 2; mt++) {
#pragma unroll
                for (int nt = 0; nt < 4; nt++) {
                    float* d = acc[mt][nt];
                    float s0 = __shfl_xor_sync(0xFFFFFFFFu, d[0], 1);
                    float s1 = __shfl_xor_sync(0xFFFFFFFFu, d[1], 1);
                    float s2 = __shfl_xor_sync(0xFFFFFFFFu, d[2], 1);
                    float s3 = __shfl_xor_sync(0xFFFFFFFFu, d[3], 1);
                    float q0, q1, q2, q3; int r;
                    if (evenlane) { q0 = d[0]; q1 = d[1]; q2 = s0; q3 = s1; r = rbase; }
                    else          { q0 = s2; q1 = s3; q2 = d[2]; q3 = d[3]; r = rbase + 8; }
                    const int n = n0 + wn * 32 + nt * 8 + (c2 >> 1) * 4;  // gate base (j*4)
                    const int j = n >> 2;
                    const int b = m0 + wm * 32 + mt * 16 + r;
                    const float4 bb4 = *reinterpret_cast<const float4*>(br + n);
                    float iv = sigf(q0 + bb4.x);
                    float fv = sigf(q1 + bb4.y);
                    float gv = tanhf_(q2 + bb4.z);
                    float ov = sigf(q3 + bb4.w);
                    float cn = fv * creg[mt * 4 + nt] + iv * gv;
                    creg[mt * 4 + nt] = cn;
                    float hn = ov * tanhf_(cn);
                    ho[b * HH + j] = __float2half_rn(hn);
                }
            }
        }

        // preload next step's x-chunk (stage 0) while waiting for the barrier
        if (step + 1 <= SS) {
            __syncthreads();   // ensure no warp is still reading stage 0 (chunk nch-1)
            const __half* nx = (step + 1 < SS) ? (g_X + (size_t)(step + 1) * BB * FF)
                                               : (g_X + (size_t)(SS - 1) * BB * FF);
            const __half* nB = (step + 1 == SS) ? g_B_dec : g_B_enc;
            const uint32_t base = sb;   // stage 0
            load_sub(base, base + 32768, nx, FF, 0, nB, KTOT, 0);
            cp_commit();
            preloaded = true;
        }

        grid_barrier(128u * (unsigned)(step + 1));

        if (dec) {
            // ---------------- pred = h_t @ Wfc^T + bfc (output only, no feedback) ----
            const int tdec = step - SS;
            __half* fcb = reinterpret_cast<__half*>(smem + FC_OFF);
            const int b0 = cta * 2;
            const __half* hsrc = g_H[pp ^ 1];
            for (int i = tid; i < 256; i += 256) {
                int rrow = i >> 7, o = i & 127;
                uint4 v = __ldcg(reinterpret_cast<const uint4*>(
                    hsrc + (size_t)(b0 + rrow) * HH) + o);
                reinterpret_cast<uint4*>(fcb)[i] = v;
            }
            __syncthreads();
            if (tid < 128) {
                int bl_ = tid >> 6, f = tid & 63;
                const float4* w4 = reinterpret_cast<const float4*>(Wfc + (size_t)f * HH);
                const __half2* h2 = reinterpret_cast<const __half2*>(fcb + bl_ * HH);
                float s = bfc[f];
#pragma unroll 4
                for (int k = 0; k < HH / 4; k++) {
                    float4 wv = w4[k];
                    float2 fa = __half22float2(h2[2 * k]);
                    float2 fb = __half22float2(h2[2 * k + 1]);
                    s += wv.x * fa.x + wv.y * fa.y + wv.z * fb.x + wv.w * fb.y;
                }
                int b = b0 + bl_;
                out[(size_t)b * TT * FF + (size_t)tdec * FF + f] = s;
            }
            __syncthreads();   // fcb region precedes next step's smem reuse
        }
    }
}

// ---------------- launch ----------------
extern "C" void kernel_launch(void* const* d_in, const int* in_sizes, int n_in,
                              void* d_out, int out_size)
{
    const float* x     = (const float*)d_in[0];
    const float* Wih_e = (const float*)d_in[1];
    const float* Whh_e = (const float*)d_in[2];
    const float* bih_e = (const float*)d_in[3];
    const float* bhh_e = (const float*)d_in[4];
    const float* Wih_d = (const float*)d_in[5];
    const float* Whh_d = (const float*)d_in[6];
    const float* bih_d = (const float*)d_in[7];
    const float* bhh_d = (const float*)d_in[8];
    const float* Wfc   = (const float*)d_in[9];
    const float* bfc   = (const float*)d_in[10];
    float* out = (float*)d_out;

    cudaFuncSetAttribute(lstm_persistent, cudaFuncAttributeMaxDynamicSharedMemorySize, SMEM_BYTES);

    prep_w<<<1024, 256>>>(Wih_e, Whh_e, bih_e, bhh_e, 0);
    prep_w<<<1024, 256>>>(Wih_d, Whh_d, bih_d, bhh_d, 1);
    { dim3 g(16, 16); prep_wcomb<<<g, 256>>>(Wih_d, Whh_d, bih_d, bhh_d, Wfc, bfc); }
    prep_x<<<1024, 256>>>(x);
    zero_kernel<<<512, 256>>>();

    dim3 grid(GG / BN, BB / BM);   // (64, 2) = 128 CTAs, one wave
    lstm_persistent<<<grid, 256, SMEM_BYTES>>>(Wfc, bfc, out);
}

// round 14
// speedup vs baseline: 5.2107x; 1.0795x over previous
#include <cuda_runtime.h>
#include <cuda_fp16.h>
#include <cstdint>
#include <cstddef>

// Problem constants
#define BB 256      // batch
#define SS 512      // encoder sequence length
#define FF 64       // feature dim
#define HH 1024     // hidden dim
#define GG 4096     // 4*H gate rows
#define KTOT 1088   // F + H
#define TT 64       // prediction length
#define NSTEP (SS + TT)

// Tiling: B (weights) fully smem-resident (17 x 8KB subs); A double-buffered 128-wide
#define BM 128
#define BN 64
#define BRES (17 * 8192)               // resident B: 139,264 B
#define ASTG 32768                     // one A stage: 2 x 16KB subs
#define SMEM_BYTES (BRES + 2 * ASTG)   // 204,800 B

// ---------------- device globals ----------------
__device__ __align__(16) __half g_B_enc[GG * KTOT];   // enc weights fp16, rows j*4+g, K-major
__device__ __align__(16) __half g_B_dec[GG * KTOT];   // dec step-SS weights (has x part)
__device__ __align__(16) __half g_B_de[GG * HH];      // dec folded weights: Whh + Wih@Wfc
__device__ __align__(16) float g_br_enc[GG];          // combined bias, reordered
__device__ __align__(16) float g_br_dec[GG];
__device__ __align__(16) float g_br_de[GG];           // folded bias: b_dec + Wih@bfc
__device__ __align__(16) __half g_X[SS * BB * FF];    // encoder x, [t][b][f], fp16
__device__ __align__(16) __half g_H[2][BB * HH];      // hidden state fp16 (ping-pong)
__device__ unsigned g_bar;                            // grid barrier counter

// ---------------- helpers ----------------
__device__ __forceinline__ uint32_t smem_u32(const void* p) {
    return (uint32_t)__cvta_generic_to_shared(p);
}
// L2-only: activations change across steps (persistent kernel -> no L1 flush)
__device__ __forceinline__ void cp16cg(uint32_t dst, const void* src) {
    asm volatile("cp.async.cg.shared.global [%0], [%1], 16;\n" :: "r"(dst), "l"(src));
}
// L1-cached: immutable weights
__device__ __forceinline__ void cp16ca(uint32_t dst, const void* src) {
    asm volatile("cp.async.ca.shared.global [%0], [%1], 16;\n" :: "r"(dst), "l"(src));
}
__device__ __forceinline__ void cp_commit() { asm volatile("cp.async.commit_group;\n"); }
__device__ __forceinline__ void cp_wait0()  { asm volatile("cp.async.wait_group 0;\n" ::: "memory"); }

__device__ __forceinline__ float sigf(float x)   { return 1.f / (1.f + __expf(-x)); }
__device__ __forceinline__ float tanhf_(float x) { return 2.f / (1.f + __expf(-2.f * x)) - 1.f; }

__device__ __forceinline__ void ldsm4(uint32_t* r, uint32_t addr) {
    asm volatile("ldmatrix.sync.aligned.m8n8.x4.shared.b16 {%0,%1,%2,%3}, [%4];"
        : "=r"(r[0]), "=r"(r[1]), "=r"(r[2]), "=r"(r[3]) : "r"(addr));
}
__device__ __forceinline__ void mma16816(float* d, const uint32_t* a, uint32_t b0, uint32_t b1) {
    asm volatile(
        "mma.sync.aligned.m16n8k16.row.col.f32.f16.f16.f32 "
        "{%0,%1,%2,%3}, {%4,%5,%6,%7}, {%8,%9}, {%0,%1,%2,%3};"
        : "+f"(d[0]), "+f"(d[1]), "+f"(d[2]), "+f"(d[3])
        : "r"(a[0]), "r"(a[1]), "r"(a[2]), "r"(a[3]), "r"(b0), "r"(b1));
}

// grid barrier: 128 CTAs, all resident (single wave)
__device__ __forceinline__ void grid_barrier(unsigned target) {
    __threadfence();
    __syncthreads();
    if (threadIdx.x == 0) {
        atomicAdd(&g_bar, 1u);
        while (*(volatile unsigned*)&g_bar < target) __nanosleep(32);
    }
    __syncthreads();
    __threadfence();
}

// ---------------- prep kernels ----------------
__global__ void prep_w(const float* __restrict__ Wih, const float* __restrict__ Whh,
                       const float* __restrict__ bih, const float* __restrict__ bhh,
                       int dec)
{
    __half* B = dec ? g_B_dec : g_B_enc;
    float* br = dec ? g_br_dec : g_br_enc;
    const int total = GG * KTOT;
    for (int idx = blockIdx.x * blockDim.x + threadIdx.x; idx < total;
         idx += gridDim.x * blockDim.x) {
        int r = idx / KTOT, k = idx - r * KTOT;
        int j = r >> 2, gg = r & 3;
        int srow = gg * HH + j;
        float w = (k < FF) ? Wih[srow * FF + k] : Whh[(size_t)srow * HH + (k - FF)];
        B[idx] = __float2half_rn(w);
    }
    for (int r = blockIdx.x * blockDim.x + threadIdx.x; r < GG;
         r += gridDim.x * blockDim.x) {
        int j = r >> 2, gg = r & 3;
        br[r] = bih[gg * HH + j] + bhh[gg * HH + j];
    }
}

// folded decoder weights: W_eff = W_hh_dec + W_ih_dec @ Wfc ; b_eff = b_dec + W_ih_dec @ bfc
__global__ void prep_wcomb(const float* __restrict__ Wih_d, const float* __restrict__ Whh_d,
                           const float* __restrict__ bih_d, const float* __restrict__ bhh_d,
                           const float* __restrict__ Wfc, const float* __restrict__ bfc)
{
    __shared__ float wt[64][65];       // Wfc[f][k0+kk]
    const int k0 = blockIdx.x * 64;
    const int r0 = blockIdx.y * 256;
    const int tid = threadIdx.x;
    for (int i = tid; i < 64 * 64; i += 256) {
        int f = i >> 6, kk = i & 63;
        wt[f][kk] = Wfc[f * HH + k0 + kk];
    }
    __syncthreads();
    const int kk = tid & 63;
    const int rr = tid >> 6;           // 0..3
    for (int r = r0 + rr; r < r0 + 256; r += 4) {
        int j = r >> 2, gg = r & 3, srow = gg * HH + j;
        const float* wi = Wih_d + srow * FF;
        float s = Whh_d[(size_t)srow * HH + k0 + kk];
#pragma unroll 16
        for (int f = 0; f < 64; f++) s += wi[f] * wt[f][kk];
        g_B_de[(size_t)r * HH + k0 + kk] = __float2half_rn(s);
    }
    if (blockIdx.x == 0) {
        for (int r = r0 + tid; r < r0 + 256; r += 256) {
            int j = r >> 2, gg = r & 3, srow = gg * HH + j;
            float s = bih_d[srow] + bhh_d[srow];
            const float* wi = Wih_d + srow * FF;
#pragma unroll 16
            for (int f = 0; f < 64; f++) s += wi[f] * bfc[f];
            g_br_de[r] = s;
        }
    }
}

__global__ void prep_x(const float* __restrict__ x)
{
    const int total = SS * BB * FF;
    for (int idx = blockIdx.x * blockDim.x + threadIdx.x; idx < total;
         idx += gridDim.x * blockDim.x) {
        int t = idx / (BB * FF);
        int rem = idx - t * (BB * FF);
        int b = rem / FF, f = rem - b * FF;
        g_X[idx] = __float2half_rn(x[(size_t)b * SS * FF + (size_t)t * FF + f]);
    }
}

__global__ void zero_kernel()
{
    if (blockIdx.x == 0 && threadIdx.x == 0) g_bar = 0;
    for (int i = blockIdx.x * blockDim.x + threadIdx.x; i < BB * HH;
         i += gridDim.x * blockDim.x) {
        g_H[0][i] = __float2half_rn(0.f);
    }
}

// ---------------- persistent fused LSTM ----------------
// grid (GG/BN=64, BB/BM=2) = 128 CTAs, 256 threads (8 warps, 4M x 2N), warp tile 32x32.
// B (weights) is smem-RESIDENT: loaded once for enc, reloaded twice at phase changes.
// Per-step loads are A-only. Cell state c in registers. One grid barrier per step.
__global__ __launch_bounds__(256, 1)
void lstm_persistent(const float* __restrict__ Wfc, const float* __restrict__ bfc,
                     float* __restrict__ out)
{
    extern __shared__ __align__(128) char smem[];
    const uint32_t sb = smem_u32(smem);
    const int tid  = threadIdx.x;
    const int lane = tid & 31;
    const int wid  = tid >> 5;
    const int wm   = wid & 3;          // 0..3 (M)
    const int wn   = wid >> 2;         // 0..1 (N)
    const int n0   = blockIdx.x * BN;
    const int m0   = blockIdx.y * BM;
    const int cta  = blockIdx.y * 64 + blockIdx.x;

    const int lr = lane & 15, lh = lane >> 4;
    const int rA0 = wm * 32 + lr, rA1 = rA0 + 16;
    const int rB0 = wn * 32 + lr, rB1 = rB0 + 16;
    const int c2 = lane & 3;
    const bool evenlane = !(c2 & 1);
    const int rbase = lane >> 2;

    float creg[8];                     // persistent cell state, one per (mt,nt)
#pragma unroll
    for (int i = 0; i < 8; i++) creg[i] = 0.f;

    // ---- loaders ----
    // B sub k (64 K-cols) into resident region at k*8192
    auto load_bsub = [&](int k, const __half* B_, int bstr) {
#pragma unroll
        for (int i = 0; i < 2; i++) {
            int idx = tid + i * 256;
            int row = idx >> 3, q = idx & 7;
            uint32_t sw = (uint32_t)(row * 128) + ((q ^ (row & 7)) << 4);
            cp16ca(sb + (uint32_t)k * 8192 + sw,
                   B_ + (size_t)(n0 + row) * bstr + k * 64 + q * 8);
        }
    };
    // A sub (128 rows x 64 K-cols) into aBase
    auto load_asub = [&](uint32_t aBase, const __half* ap, int astr, int ak) {
#pragma unroll
        for (int i = 0; i < 4; i++) {
            int idx = tid + i * 256;
            int row = idx >> 3, q = idx & 7;
            uint32_t sw = (uint32_t)(row * 128) + ((q ^ (row & 7)) << 4);
            cp16cg(aBase + sw, ap + (size_t)(m0 + row) * astr + ak + q * 8);
        }
    };

    // initial B residency (encoder weights), before the step loop
    for (int k = 0; k < 17; k++) load_bsub(k, g_B_enc, KTOT);
    cp_commit();

    bool preloaded = false;

    for (int step = 0; step < NSTEP; step++) {
        const bool de = (step > SS);           // folded decoder steps (K=1024)
        const bool dec = (step >= SS);
        const int pp = step & 1;
        const int nch = de ? 8 : 9;
        const float* __restrict__ br = de ? g_br_de : (dec ? g_br_dec : g_br_enc);
        const __half* __restrict__ xp = (step < SS)
            ? g_X + (size_t)step * BB * FF
            : g_X + (size_t)(SS - 1) * BB * FF;   // step == SS; unused for de
        const __half* __restrict__ hp = g_H[pp];

        // A chunk c into stage s. enc chunk0 = x (1 sub); else 2 h subs.
        auto load_chunk = [&](int c, int s) {
            const uint32_t base = sb + BRES + (uint32_t)s * ASTG;
            if (de) {
                load_asub(base,         hp, HH, c * 128);
                load_asub(base + 16384, hp, HH, c * 128 + 64);
            } else if (c == 0) {
                load_asub(base, xp, FF, 0);
            } else {
                load_asub(base,         hp, HH, (c - 1) * 128);
                load_asub(base + 16384, hp, HH, (c - 1) * 128 + 64);
            }
            cp_commit();
        };

        float acc[2][4][4];
#pragma unroll
        for (int mt = 0; mt < 2; mt++)
#pragma unroll
            for (int nt = 0; nt < 4; nt++)
#pragma unroll
                for (int i = 0; i < 4; i++) acc[mt][nt][i] = 0.f;

        if (!preloaded) load_chunk(0, 0);
        preloaded = false;

        for (int c = 0; c < nch; c++) {
            const int s = c & 1;
            cp_wait0();
            __syncthreads();
            if (c + 1 < nch) load_chunk(c + 1, s ^ 1);

            const int nsub = (!de && c == 0) ? 1 : 2;
            for (int sub = 0; sub < nsub; sub++) {
                const uint32_t ab = sb + BRES + (uint32_t)s * ASTG + sub * 16384;
                const int bsub = de ? (2 * c + sub) : (c == 0 ? 0 : 2 * c - 1 + sub);
                const uint32_t bb = sb + (uint32_t)bsub * 8192;
#pragma unroll
                for (int ks = 0; ks < 4; ks++) {
                    const int qk = (ks << 1) | lh;
                    uint32_t a0[4], a1[4], b0[4], b1[4];
                    ldsm4(a0, ab + rA0 * 128 + ((qk ^ (rA0 & 7)) << 4));
                    ldsm4(a1, ab + rA1 * 128 + ((qk ^ (rA1 & 7)) << 4));
                    ldsm4(b0, bb + rB0 * 128 + ((qk ^ (rB0 & 7)) << 4));
                    ldsm4(b1, bb + rB1 * 128 + ((qk ^ (rB1 & 7)) << 4));
                    mma16816(acc[0][0], a0, b0[0], b0[2]);
                    mma16816(acc[0][1], a0, b0[1], b0[3]);
                    mma16816(acc[0][2], a0, b1[0], b1[2]);
                    mma16816(acc[0][3], a0, b1[1], b1[3]);
                    mma16816(acc[1][0], a1, b0[0], b0[2]);
                    mma16816(acc[1][1], a1, b0[1], b0[3]);
                    mma16816(acc[1][2], a1, b1[0], b1[2]);
                    mma16816(acc[1][3], a1, b1[1], b1[3]);
                }
            }
        }

        // ---------------- fused LSTM epilogue (c in registers, h fp16) ----------
        {
            __half* __restrict__ ho = g_H[pp ^ 1];
#pragma unroll
            for (int mt = 0; mt < 2; mt++) {
#pragma unroll
                for (int nt = 0; nt < 4; nt++) {
                    float* d = acc[mt][nt];
                    float s0 = __shfl_xor_sync(0xFFFFFFFFu, d[0], 1);
                    float s1 = __shfl_xor_sync(0xFFFFFFFFu, d[1], 1);
                    float s2 = __shfl_xor_sync(0xFFFFFFFFu, d[2], 1);
                    float s3 = __shfl_xor_sync(0xFFFFFFFFu, d[3], 1);
                    float q0, q1, q2, q3; int r;
                    if (evenlane) { q0 = d[0]; q1 = d[1]; q2 = s0; q3 = s1; r = rbase; }
                    else          { q0 = s2; q1 = s3; q2 = d[2]; q3 = d[3]; r = rbase + 8; }
                    const int n = n0 + wn * 32 + nt * 8 + (c2 >> 1) * 4;  // gate base (j*4)
                    const int j = n >> 2;
                    const int b = m0 + wm * 32 + mt * 16 + r;
                    const float4 bb4 = *reinterpret_cast<const float4*>(br + n);
                    float iv = sigf(q0 + bb4.x);
                    float fv = sigf(q1 + bb4.y);
                    float gv = tanhf_(q2 + bb4.z);
                    float ov = sigf(q3 + bb4.w);
                    float cn = fv * creg[mt * 4 + nt] + iv * gv;
                    creg[mt * 4 + nt] = cn;
                    float hn = ov * tanhf_(cn);
                    ho[b * HH + j] = __float2half_rn(hn);
                }
            }
        }

        // phase-transition B reloads + next-x preload, overlapped with barrier wait
        {
            const bool reloadDec = (step + 1 == SS);
            const bool reloadDe  = (step + 1 == SS + 1);
            const bool pre = (step + 1 <= SS);
            if (reloadDec || reloadDe || pre) {
                __syncthreads();   // all warps done reading B/A smem of this step
                if (reloadDec) for (int k = 0; k < 17; k++) load_bsub(k, g_B_dec, KTOT);
                if (reloadDe)  for (int k = 0; k < 16; k++) load_bsub(k, g_B_de, HH);
                if (pre) {
                    const __half* nx = (step + 1 < SS)
                        ? (g_X + (size_t)(step + 1) * BB * FF)
                        : (g_X + (size_t)(SS - 1) * BB * FF);
                    load_asub(sb + BRES, nx, FF, 0);   // stage 0, sub 0
                    preloaded = true;
                }
                cp_commit();
            }
        }

        grid_barrier(128u * (unsigned)(step + 1));

        if (dec) {
            // ---------------- pred = h_t @ Wfc^T + bfc (output only) ----------------
            const int tdec = step - SS;
            __half* fcb = reinterpret_cast<__half*>(smem + BRES);  // A stage 0 (free)
            const int b0 = cta * 2;
            const __half* hsrc = g_H[pp ^ 1];
            for (int i = tid; i < 256; i += 256) {
                int rrow = i >> 7, o = i & 127;
                uint4 v = __ldcg(reinterpret_cast<const uint4*>(
                    hsrc + (size_t)(b0 + rrow) * HH) + o);
                reinterpret_cast<uint4*>(fcb)[i] = v;
            }
            __syncthreads();
            if (tid < 128) {
                int bl_ = tid >> 6, f = tid & 63;
                const float4* w4 = reinterpret_cast<const float4*>(Wfc + (size_t)f * HH);
                const __half2* h2 = reinterpret_cast<const __half2*>(fcb + bl_ * HH);
                float s = bfc[f];
#pragma unroll 4
                for (int k = 0; k < HH / 4; k++) {
                    float4 wv = w4[k];
                    float2 fa = __half22float2(h2[2 * k]);
                    float2 fb = __half22float2(h2[2 * k + 1]);
                    s += wv.x * fa.x + wv.y * fa.y + wv.z * fb.x + wv.w * fb.y;
                }
                int b = b0 + bl_;
                out[(size_t)b * TT * FF + (size_t)tdec * FF + f] = s;
            }
            __syncthreads();   // fcb = A stage 0; next step's chunk0 load follows
        }
    }
}

// ---------------- launch ----------------
extern "C" void kernel_launch(void* const* d_in, const int* in_sizes, int n_in,
                              void* d_out, int out_size)
{
    const float* x     = (const float*)d_in[0];
    const float* Wih_e = (const float*)d_in[1];
    const float* Whh_e = (const float*)d_in[2];
    const float* bih_e = (const float*)d_in[3];
    const float* bhh_e = (const float*)d_in[4];
    const float* Wih_d = (const float*)d_in[5];
    const float* Whh_d = (const float*)d_in[6];
    const float* bih_d = (const float*)d_in[7];
    const float* bhh_d = (const float*)d_in[8];
    const float* Wfc   = (const float*)d_in[9];
    const float* bfc   = (const float*)d_in[10];
    float* out = (float*)d_out;

    cudaFuncSetAttribute(lstm_persistent, cudaFuncAttributeMaxDynamicSharedMemorySize, SMEM_BYTES);

    prep_w<<<1024, 256>>>(Wih_e, Whh_e, bih_e, bhh_e, 0);
    prep_w<<<1024, 256>>>(Wih_d, Whh_d, bih_d, bhh_d, 1);
    { dim3 g(16, 16); prep_wcomb<<<g, 256>>>(Wih_d, Whh_d, bih_d, bhh_d, Wfc, bfc); }
    prep_x<<<1024, 256>>>(x);
    zero_kernel<<<512, 256>>>();

    dim3 grid(GG / BN, BB / BM);   // (64, 2) = 128 CTAs, one wave
    lstm_persistent<<<grid, 256, SMEM_BYTES>>>(Wfc, bfc, out);
}

// round 15
// speedup vs baseline: 5.3885x; 1.0341x over previous
#include <cuda_runtime.h>
#include <cuda_fp16.h>
#include <cstdint>
#include <cstddef>

// Problem constants
#define BB 256      // batch
#define SS 512      // encoder sequence length
#define FF 64       // feature dim
#define HH 1024     // hidden dim
#define GG 4096     // 4*H gate rows
#define KTOT 1088   // F + H
#define TT 64       // prediction length
#define NSTEP (SS + TT)

// Tiling: B (weights) smem-resident (17 x 8KB); A double-buffered; 4KB h-staging
#define BM 128
#define BN 64
#define BRES (17 * 8192)               // resident B: 139,264 B
#define ASTG 32768                     // one A stage: 2 x 16KB subs
#define HST_OFF (BRES + 2 * ASTG)      // h staging (4KB) / fc scratch
#define SMEM_BYTES (HST_OFF + 8192)

// ---------------- device globals ----------------
__device__ __align__(16) __half g_B_enc[GG * KTOT];   // enc weights fp16, rows j*4+g, K-major
__device__ __align__(16) __half g_B_dec[GG * KTOT];   // dec step-SS weights (has x part)
__device__ __align__(16) __half g_B_de[GG * HH];      // dec folded weights: Whh + Wih@Wfc
__device__ __align__(16) float g_br_enc[GG];          // combined bias, reordered
__device__ __align__(16) float g_br_dec[GG];
__device__ __align__(16) float g_br_de[GG];           // folded bias: b_dec + Wih@bfc
__device__ __align__(16) __half g_X[SS * BB * FF];    // encoder x, [t][b][f], fp16
__device__ __align__(16) __half g_H[2][BB * HH];      // hidden state fp16 (ping-pong)
__device__ unsigned g_bars[32];                       // distributed barrier counters

// ---------------- helpers ----------------
__device__ __forceinline__ uint32_t smem_u32(const void* p) {
    return (uint32_t)__cvta_generic_to_shared(p);
}
// L2-only: activations change across steps (persistent kernel -> no L1 flush)
__device__ __forceinline__ void cp16cg(uint32_t dst, const void* src) {
    asm volatile("cp.async.cg.shared.global [%0], [%1], 16;\n" :: "r"(dst), "l"(src));
}
// L1-cached: immutable weights
__device__ __forceinline__ void cp16ca(uint32_t dst, const void* src) {
    asm volatile("cp.async.ca.shared.global [%0], [%1], 16;\n" :: "r"(dst), "l"(src));
}
__device__ __forceinline__ void cp_commit() { asm volatile("cp.async.commit_group;\n"); }
__device__ __forceinline__ void cp_wait0()  { asm volatile("cp.async.wait_group 0;\n" ::: "memory"); }

__device__ __forceinline__ float sigf(float x)   { return 1.f / (1.f + __expf(-x)); }
__device__ __forceinline__ float tanhf_(float x) { return 2.f / (1.f + __expf(-2.f * x)) - 1.f; }

__device__ __forceinline__ void ldsm4(uint32_t* r, uint32_t addr) {
    asm volatile("ldmatrix.sync.aligned.m8n8.x4.shared.b16 {%0,%1,%2,%3}, [%4];"
        : "=r"(r[0]), "=r"(r[1]), "=r"(r[2]), "=r"(r[3]) : "r"(addr));
}
__device__ __forceinline__ void mma16816(float* d, const uint32_t* a, uint32_t b0, uint32_t b1) {
    asm volatile(
        "mma.sync.aligned.m16n8k16.row.col.f32.f16.f16.f32 "
        "{%0,%1,%2,%3}, {%4,%5,%6,%7}, {%8,%9}, {%0,%1,%2,%3};"
        : "+f"(d[0]), "+f"(d[1]), "+f"(d[2]), "+f"(d[3])
        : "r"(a[0]), "r"(a[1]), "r"(a[2]), "r"(a[3]), "r"(b0), "r"(b1));
}

// pair barrier: the two warps sharing wm (64 threads), named barrier id wm+1
__device__ __forceinline__ void bar_pair(int wm) {
    asm volatile("bar.sync %0, %1;" :: "r"(wm + 1), "r"(64) : "memory");
}

// distributed grid barrier: 128 CTAs over 32 counters (4 each); warp0 polls all
__device__ __forceinline__ void grid_barrier(int cta, unsigned target4) {
    __threadfence();
    __syncthreads();
    if (threadIdx.x == 0) atomicAdd(&g_bars[cta & 31], 1u);
    if (threadIdx.x < 32) {
        unsigned v;
        for (;;) {
            asm volatile("ld.global.cg.u32 %0, [%1];"
                         : "=r"(v) : "l"(g_bars + threadIdx.x) : "memory");
            if (__all_sync(0xFFFFFFFFu, v >= target4)) break;
            __nanosleep(20);
        }
    }
    __syncthreads();
    __threadfence();
}

// ---------------- prep kernels ----------------
__global__ void prep_w(const float* __restrict__ Wih, const float* __restrict__ Whh,
                       const float* __restrict__ bih, const float* __restrict__ bhh,
                       int dec)
{
    __half* B = dec ? g_B_dec : g_B_enc;
    float* br = dec ? g_br_dec : g_br_enc;
    const int total = GG * KTOT;
    for (int idx = blockIdx.x * blockDim.x + threadIdx.x; idx < total;
         idx += gridDim.x * blockDim.x) {
        int r = idx / KTOT, k = idx - r * KTOT;
        int j = r >> 2, gg = r & 3;
        int srow = gg * HH + j;
        float w = (k < FF) ? Wih[srow * FF + k] : Whh[(size_t)srow * HH + (k - FF)];
        B[idx] = __float2half_rn(w);
    }
    for (int r = blockIdx.x * blockDim.x + threadIdx.x; r < GG;
         r += gridDim.x * blockDim.x) {
        int j = r >> 2, gg = r & 3;
        br[r] = bih[gg * HH + j] + bhh[gg * HH + j];
    }
}

// folded decoder weights: W_eff = W_hh_dec + W_ih_dec @ Wfc ; b_eff = b_dec + W_ih_dec @ bfc
__global__ void prep_wcomb(const float* __restrict__ Wih_d, const float* __restrict__ Whh_d,
                           const float* __restrict__ bih_d, const float* __restrict__ bhh_d,
                           const float* __restrict__ Wfc, const float* __restrict__ bfc)
{
    __shared__ float wt[64][65];       // Wfc[f][k0+kk]
    const int k0 = blockIdx.x * 64;
    const int r0 = blockIdx.y * 256;
    const int tid = threadIdx.x;
    for (int i = tid; i < 64 * 64; i += 256) {
        int f = i >> 6, kk = i & 63;
        wt[f][kk] = Wfc[f * HH + k0 + kk];
    }
    __syncthreads();
    const int kk = tid & 63;
    const int rr = tid >> 6;           // 0..3
    for (int r = r0 + rr; r < r0 + 256; r += 4) {
        int j = r >> 2, gg = r & 3, srow = gg * HH + j;
        const float* wi = Wih_d + srow * FF;
        float s = Whh_d[(size_t)srow * HH + k0 + kk];
#pragma unroll 16
        for (int f = 0; f < 64; f++) s += wi[f] * wt[f][kk];
        g_B_de[(size_t)r * HH + k0 + kk] = __float2half_rn(s);
    }
    if (blockIdx.x == 0) {
        for (int r = r0 + tid; r < r0 + 256; r += 256) {
            int j = r >> 2, gg = r & 3, srow = gg * HH + j;
            float s = bih_d[srow] + bhh_d[srow];
            const float* wi = Wih_d + srow * FF;
#pragma unroll 16
            for (int f = 0; f < 64; f++) s += wi[f] * bfc[f];
            g_br_de[r] = s;
        }
    }
}

__global__ void prep_x(const float* __restrict__ x)
{
    const int total = SS * BB * FF;
    for (int idx = blockIdx.x * blockDim.x + threadIdx.x; idx < total;
         idx += gridDim.x * blockDim.x) {
        int t = idx / (BB * FF);
        int rem = idx - t * (BB * FF);
        int b = rem / FF, f = rem - b * FF;
        g_X[idx] = __float2half_rn(x[(size_t)b * SS * FF + (size_t)t * FF + f]);
    }
}

__global__ void zero_kernel()
{
    if (blockIdx.x == 0 && threadIdx.x < 32) g_bars[threadIdx.x] = 0;
    for (int i = blockIdx.x * blockDim.x + threadIdx.x; i < BB * HH;
         i += gridDim.x * blockDim.x) {
        g_H[0][i] = __float2half_rn(0.f);
    }
}

// ---------------- persistent fused LSTM ----------------
// grid (64, 2) = 128 CTAs, 256 threads (8 warps, 4M x 2N), warp tile 32x32.
// B smem-resident; A loads PAIR-SCOPED (warp pair {wm} loads its own 32 rows),
// pair barriers in the mainloop. Distributed grid barrier. Coalesced h stores.
__global__ __launch_bounds__(256, 1)
void lstm_persistent(const float* __restrict__ Wfc, const float* __restrict__ bfc,
                     float* __restrict__ out)
{
    extern __shared__ __align__(128) char smem[];
    const uint32_t sb = smem_u32(smem);
    const int tid  = threadIdx.x;
    const int lane = tid & 31;
    const int wid  = tid >> 5;
    const int wm   = wid & 3;          // 0..3 (M)  -> pair id
    const int wn   = wid >> 2;         // 0..1 (N)
    const int ptid = lane + wn * 32;   // 0..63 within pair
    const int n0   = blockIdx.x * BN;
    const int m0   = blockIdx.y * BM;
    const int cta  = blockIdx.y * 64 + blockIdx.x;

    const int lr = lane & 15, lh = lane >> 4;
    const int rA0 = wm * 32 + lr, rA1 = rA0 + 16;
    const int rB0 = wn * 32 + lr, rB1 = rB0 + 16;
    const int c2 = lane & 3;
    const bool evenlane = !(c2 & 1);
    const int rbase = lane >> 2;

    float creg[8];                     // persistent cell state
#pragma unroll
    for (int i = 0; i < 8; i++) creg[i] = 0.f;

    // B sub k (64 K-cols, all 128 B-rows) into resident region; tid-mapped (256)
    auto load_bsub = [&](int k, const __half* B_, int bstr) {
#pragma unroll
        for (int i = 0; i < 2; i++) {
            int idx = tid + i * 256;
            int row = idx >> 3, q = idx & 7;
            uint32_t sw = (uint32_t)(row * 128) + ((q ^ (row & 7)) << 4);
            cp16ca(sb + (uint32_t)k * 8192 + sw,
                   B_ + (size_t)(n0 + row) * bstr + k * 64 + q * 8);
        }
    };
    // A sub: PAIR loads its own 32 rows (wm*32..) x 64 K-cols; 4 cp16/thread
    auto load_asub = [&](uint32_t aBase, const __half* ap, int astr, int ak) {
#pragma unroll
        for (int i = 0; i < 4; i++) {
            int idx = ptid + i * 64;       // 0..255
            int row = wm * 32 + (idx >> 3);
            int q = idx & 7;
            uint32_t sw = (uint32_t)(row * 128) + ((q ^ (row & 7)) << 4);
            cp16cg(aBase + sw, ap + (size_t)(m0 + row) * astr + ak + q * 8);
        }
    };

    // initial B residency (encoder weights)
    for (int k = 0; k < 17; k++) load_bsub(k, g_B_enc, KTOT);
    cp_commit();
    cp_wait0();
    __syncthreads();

    bool preloaded = false;

    for (int step = 0; step < NSTEP; step++) {
        const bool de = (step > SS);           // folded decoder steps (K=1024)
        const bool dec = (step >= SS);
        const int pp = step & 1;
        const int nch = de ? 8 : 9;
        const float* __restrict__ br = de ? g_br_de : (dec ? g_br_dec : g_br_enc);
        const __half* __restrict__ xp = (step < SS)
            ? g_X + (size_t)step * BB * FF
            : g_X + (size_t)(SS - 1) * BB * FF;
        const __half* __restrict__ hp = g_H[pp];

        // A chunk c into stage s (pair-scoped). enc chunk0 = x (1 sub); else 2 h subs.
        auto load_chunk = [&](int c, int s) {
            const uint32_t base = sb + BRES + (uint32_t)s * ASTG;
            if (de) {
                load_asub(base,         hp, HH, c * 128);
                load_asub(base + 16384, hp, HH, c * 128 + 64);
            } else if (c == 0) {
                load_asub(base, xp, FF, 0);
            } else {
                load_asub(base,         hp, HH, (c - 1) * 128);
                load_asub(base + 16384, hp, HH, (c - 1) * 128 + 64);
            }
            cp_commit();
        };

        float acc[2][4][4];
#pragma unroll
        for (int mt = 0; mt < 2; mt++)
#pragma unroll
            for (int nt = 0; nt < 4; nt++)
#pragma unroll
                for (int i = 0; i < 4; i++) acc[mt][nt][i] = 0.f;

        if (!preloaded) load_chunk(0, 0);
        preloaded = false;

        for (int c = 0; c < nch; c++) {
            const int s = c & 1;
            cp_wait0();
            bar_pair(wm);
            if (c + 1 < nch) load_chunk(c + 1, s ^ 1);

            const int nsub = (!de && c == 0) ? 1 : 2;
            for (int sub = 0; sub < nsub; sub++) {
                const uint32_t ab = sb + BRES + (uint32_t)s * ASTG + sub * 16384;
                const int bsub = de ? (2 * c + sub) : (c == 0 ? 0 : 2 * c - 1 + sub);
                const uint32_t bb = sb + (uint32_t)bsub * 8192;
#pragma unroll
                for (int ks = 0; ks < 4; ks++) {
                    const int qk = (ks << 1) | lh;
                    uint32_t a0[4], a1[4], b0[4], b1[4];
                    ldsm4(a0, ab + rA0 * 128 + ((qk ^ (rA0 & 7)) << 4));
                    ldsm4(a1, ab + rA1 * 128 + ((qk ^ (rA1 & 7)) << 4));
                    ldsm4(b0, bb + rB0 * 128 + ((qk ^ (rB0 & 7)) << 4));
                    ldsm4(b1, bb + rB1 * 128 + ((qk ^ (rB1 & 7)) << 4));
                    mma16816(acc[0][0], a0, b0[0], b0[2]);
                    mma16816(acc[0][1], a0, b0[1], b0[3]);
                    mma16816(acc[0][2], a0, b1[0], b1[2]);
                    mma16816(acc[0][3], a0, b1[1], b1[3]);
                    mma16816(acc[1][0], a1, b0[0], b0[2]);
                    mma16816(acc[1][1], a1, b0[1], b0[3]);
                    mma16816(acc[1][2], a1, b1[0], b1[2]);
                    mma16816(acc[1][3], a1, b1[1], b1[3]);
                }
            }
        }

        // ---------------- fused LSTM epilogue: smem-staged, pair-coalesced ------
        {
            __half* __restrict__ ho = g_H[pp ^ 1];
            __half* hstg = reinterpret_cast<__half*>(smem + HST_OFF) + wm * 512;
            // staging layout per pair: [32 rows][16 j], 2B each = 1KB
#pragma unroll
            for (int mt = 0; mt < 2; mt++) {
#pragma unroll
                for (int nt = 0; nt < 4; nt++) {
                    float* d = acc[mt][nt];
                    float s0 = __shfl_xor_sync(0xFFFFFFFFu, d[0], 1);
                    float s1 = __shfl_xor_sync(0xFFFFFFFFu, d[1], 1);
                    float s2 = __shfl_xor_sync(0xFFFFFFFFu, d[2], 1);
                    float s3 = __shfl_xor_sync(0xFFFFFFFFu, d[3], 1);
                    float q0, q1, q2, q3; int r;
                    if (evenlane) { q0 = d[0]; q1 = d[1]; q2 = s0; q3 = s1; r = rbase; }
                    else          { q0 = s2; q1 = s3; q2 = d[2]; q3 = d[3]; r = rbase + 8; }
                    const int n = n0 + wn * 32 + nt * 8 + (c2 >> 1) * 4;  // gate base
                    const int jloc = wn * 8 + nt * 2 + (c2 >> 1);         // 0..15
                    const int lrow = mt * 16 + r;                         // 0..31
                    const float4 bb4 = *reinterpret_cast<const float4*>(br + n);
                    float iv = sigf(q0 + bb4.x);
                    float fv = sigf(q1 + bb4.y);
                    float gv = tanhf_(q2 + bb4.z);
                    float ov = sigf(q3 + bb4.w);
                    float cn = fv * creg[mt * 4 + nt] + iv * gv;
                    creg[mt * 4 + nt] = cn;
                    hstg[lrow * 16 + jloc] = __float2half_rn(ov * tanhf_(cn));
                }
            }
            bar_pair(wm);
            // coalesced store: 32 rows x 32B per pair; 1 STG.16 per thread
            {
                int row = ptid >> 1, half = ptid & 1;
                uint4 v = *reinterpret_cast<const uint4*>(hstg + row * 16 + half * 8);
                int b = m0 + wm * 32 + row;
                *reinterpret_cast<uint4*>(ho + (size_t)b * HH + (n0 >> 2) + half * 8) = v;
            }
        }

        // preload next step's x chunk (stage 0, pair rows) before the barrier
        if (step + 1 <= SS) {
            const __half* nx = (step + 1 < SS) ? (g_X + (size_t)(step + 1) * BB * FF)
                                               : (g_X + (size_t)(SS - 1) * BB * FF);
            load_asub(sb + BRES, nx, FF, 0);   // stage 0, sub 0 (own pair rows)
            cp_commit();
            preloaded = true;
        }

        // phase-transition B reloads (2 steps total; full-CTA sync around them)
        if (step + 1 == SS || step + 1 == SS + 1) {
            __syncthreads();               // all pairs done reading resident B
            if (step + 1 == SS) for (int k = 0; k < 17; k++) load_bsub(k, g_B_dec, KTOT);
            else                for (int k = 0; k < 16; k++) load_bsub(k, g_B_de, HH);
            cp_commit();
            cp_wait0();                    // also drains the x preload (harmless)
            __syncthreads();
        }

        grid_barrier(cta, 4u * (unsigned)(step + 1));

        if (dec) {
            // ---------------- pred = h_t @ Wfc^T + bfc (output only) ------------
            const int tdec = step - SS;
            __half* fcb = reinterpret_cast<__half*>(smem + HST_OFF);
            const int b0 = cta * 2;
            const __half* hsrc = g_H[pp ^ 1];
            for (int i = tid; i < 256; i += 256) {
                int rrow = i >> 7, o = i & 127;
                uint4 v = __ldcg(reinterpret_cast<const uint4*>(
                    hsrc + (size_t)(b0 + rrow) * HH) + o);
                reinterpret_cast<uint4*>(fcb)[i] = v;
            }
            __syncthreads();
            if (tid < 128) {
                int bl_ = tid >> 6, f = tid & 63;
                const float4* w4 = reinterpret_cast<const float4*>(Wfc + (size_t)f * HH);
                const __half2* h2 = reinterpret_cast<const __half2*>(fcb + bl_ * HH);
                float s = bfc[f];
#pragma unroll 4
                for (int k = 0; k < HH / 4; k++) {
                    float4 wv = w4[k];
                    float2 fa = __half22float2(h2[2 * k]);
                    float2 fb = __half22float2(h2[2 * k + 1]);
                    s += wv.x * fa.x + wv.y * fa.y + wv.z * fb.x + wv.w * fb.y;
                }
                int b = b0 + bl_;
                out[(size_t)b * TT * FF + (size_t)tdec * FF + f] = s;
            }
            __syncthreads();   // hstg/fcb region reused next step
        }
    }
}

// ---------------- launch ----------------
extern "C" void kernel_launch(void* const* d_in, const int* in_sizes, int n_in,
                              void* d_out, int out_size)
{
    const float* x     = (const float*)d_in[0];
    const float* Wih_e = (const float*)d_in[1];
    const float* Whh_e = (const float*)d_in[2];
    const float* bih_e = (const float*)d_in[3];
    const float* bhh_e = (const float*)d_in[4];
    const float* Wih_d = (const float*)d_in[5];
    const float* Whh_d = (const float*)d_in[6];
    const float* bih_d = (const float*)d_in[7];
    const float* bhh_d = (const float*)d_in[8];
    const float* Wfc   = (const float*)d_in[9];
    const float* bfc   = (const float*)d_in[10];
    float* out = (float*)d_out;

    cudaFuncSetAttribute(lstm_persistent, cudaFuncAttributeMaxDynamicSharedMemorySize, SMEM_BYTES);

    prep_w<<<1024, 256>>>(Wih_e, Whh_e, bih_e, bhh_e, 0);
    prep_w<<<1024, 256>>>(Wih_d, Whh_d, bih_d, bhh_d, 1);
    { dim3 g(16, 16); prep_wcomb<<<g, 256>>>(Wih_d, Whh_d, bih_d, bhh_d, Wfc, bfc); }
    prep_x<<<1024, 256>>>(x);
    zero_kernel<<<512, 256>>>();

    dim3 grid(GG / BN, BB / BM);   // (64, 2) = 128 CTAs, one wave
    lstm_persistent<<<grid, 256, SMEM_BYTES>>>(Wfc, bfc, out);
}